// round 12
// baseline (speedup 1.0000x reference)
#include <cuda_runtime.h>
#include <cuda_bf16.h>
#include <math.h>

#define NLEV 16
#define TBL (1u << 19)

// ---- dynamic shared layout (float units) ----
// Weight region is PHASED 3 ways behind __syncthreads():
//   phase A: W1 [32][72]=2304 @0, W2 [64][24]=1536 @2304   (3840)
//   phase B: R1 [32][72]=2304 @0                            (2304)
//   phase C: R2 [64][72]=4608 @0, R3 [64][8]=512 @4608      (5120)
// strides keep B-frag loads conflict-free (stride mod 32 in {8,24}).
#define OFF_W1 0
#define OFF_W2 2304
#define OFF_R1 0
#define OFF_R2 0
#define OFF_R3 4608
#define OFF_ACT 5120        // 4 warps x [32][68] = 8704 (stride 68: A-frags conflict-free)
#define SMEM_FLOATS 13824   // 55296 bytes -> 4 CTAs/SM
#define ASTR 68

__device__ __constant__ int c_res[16] = {16, 22, 30, 42, 58, 80, 111, 153,
                                         212, 294, 406, 561, 775, 1072, 1481, 2047};

__device__ __forceinline__ float tf32r(float x) {
    unsigned u;
    asm("cvt.rna.tf32.f32 %0, %1;" : "=r"(u) : "f"(x));
    return __uint_as_float(u);
}

__device__ __forceinline__ void mma8(float* c, const unsigned* a, const unsigned* b) {
    asm volatile(
        "mma.sync.aligned.m16n8k8.row.col.f32.tf32.tf32.f32 "
        "{%0,%1,%2,%3}, {%4,%5,%6,%7}, {%8,%9}, {%0,%1,%2,%3};\n"
        : "+f"(c[0]), "+f"(c[1]), "+f"(c[2]), "+f"(c[3])
        : "r"(a[0]), "r"(a[1]), "r"(a[2]), "r"(a[3]), "r"(b[0]), "r"(b[1]));
}

// preload A-fragments for 4 consecutive kt slices (kt0..kt0+3) into a[2][4][4]
__device__ __forceinline__ void load_a4(const float* A, int g, int t, int kt0,
                                        unsigned a[2][4][4]) {
    #pragma unroll
    for (int mt = 0; mt < 2; mt++)
    #pragma unroll
    for (int kk = 0; kk < 4; kk++) {
        const int r = mt * 16 + g, k = (kt0 + kk) * 8 + t;
        a[mt][kk][0] = __float_as_uint(A[(r    ) * ASTR + k    ]);
        a[mt][kk][1] = __float_as_uint(A[(r + 8) * ASTR + k    ]);
        a[mt][kk][2] = __float_as_uint(A[(r    ) * ASTR + k + 4]);
        a[mt][kk][3] = __float_as_uint(A[(r + 8) * ASTR + k + 4]);
    }
}

__global__ __launch_bounds__(128, 4)
void nerf_mma_kernel(const float* __restrict__ xyz,
                     const float* __restrict__ dirp,
                     const float* __restrict__ table,
                     const float* __restrict__ w1,
                     const float* __restrict__ w2,
                     const float* __restrict__ wr1,
                     const float* __restrict__ wr2,
                     const float* __restrict__ wr3,
                     float* __restrict__ out, int N)
{
    extern __shared__ __align__(16) float sm[];
    const int tid = threadIdx.x;

    // -------- phase A staging: sigma weights --------
    {
        float* sW1 = sm + OFF_W1;
        float* sW2 = sm + OFF_W2;
        for (int i = tid; i < 32 * 64; i += 128) { int r = i >> 6, c = i & 63; sW1[r * 72 + c] = tf32r(w1[i]); }
        for (int i = tid; i < 64 * 24; i += 128) {
            int r = i / 24, c = i % 24;
            sW2[i] = (c < 17) ? tf32r(w2[r * 17 + c]) : 0.0f;
        }
    }
    __syncthreads();

    const int ln = tid & 31;
    const int wp = tid >> 5;
    const int g  = ln >> 2;      // group id (0..7)
    const int t  = ln & 3;       // thread-in-group (0..3)
    float* A = sm + OFF_ACT + wp * (32 * ASTR);

    const int base = blockIdx.x * 128 + wp * 32;
    const int idx  = base + ln;
    const int pidx = idx < N ? idx : N - 1;

    // direction raw components (SH computed at write site)
    const float drx = dirp[3 * pidx + 0];
    const float dry = dirp[3 * pidx + 1];
    const float drz = dirp[3 * pidx + 2];

    // -------- hash-grid encode -> act row ln, cols 0..31 (tf32-rounded) --------
    {
        const float x = xyz[3 * pidx + 0];
        const float y = xyz[3 * pidx + 1];
        const float z = xyz[3 * pidx + 2];
        float* arow = A + ln * ASTR;

        #pragma unroll
        for (int l = 0; l < NLEV; l++) {
            const int res = c_res[l];
            const float rf = (float)res;
            const float px = x * rf, py = y * rf, pz = z * rf;
            const float fx = floorf(px), fy = floorf(py), fz = floorf(pz);
            const float wx = px - fx, wy = py - fy, wz = pz - fz;
            const unsigned X = (unsigned)fx, Y = (unsigned)fy, Z = (unsigned)fz;

            unsigned id0, id1, id2, id3, id4, id5, id6, id7;
            if (l < 5) {
                const unsigned s  = (unsigned)(res + 1);
                const unsigned s2 = s * s;
                const unsigned b0 = X + Y * s + Z * s2;
                id0 = b0;          id1 = b0 + 1u;
                id2 = b0 + s;      id3 = b0 + s + 1u;
                id4 = b0 + s2;     id5 = b0 + s2 + 1u;
                id6 = b0 + s2 + s; id7 = b0 + s2 + s + 1u;
            } else {
                const unsigned P1 = 2654435761u, P2 = 805459861u;
                const unsigned hx0 = X, hx1 = X + 1u;
                const unsigned hy0 = Y * P1, hy1 = (Y + 1u) * P1;
                const unsigned hz0 = Z * P2, hz1 = (Z + 1u) * P2;
                const unsigned M = TBL - 1u;
                id0 = (hx0 ^ hy0 ^ hz0) & M;  id1 = (hx1 ^ hy0 ^ hz0) & M;
                id2 = (hx0 ^ hy1 ^ hz0) & M;  id3 = (hx1 ^ hy1 ^ hz0) & M;
                id4 = (hx0 ^ hy0 ^ hz1) & M;  id5 = (hx1 ^ hy0 ^ hz1) & M;
                id6 = (hx0 ^ hy1 ^ hz1) & M;  id7 = (hx1 ^ hy1 ^ hz1) & M;
            }

            const float2* tl = (const float2*)table + (size_t)l * TBL;
            const float2 f0 = __ldg(tl + id0);
            const float2 f1 = __ldg(tl + id1);
            const float2 f2 = __ldg(tl + id2);
            const float2 f3 = __ldg(tl + id3);
            const float2 f4 = __ldg(tl + id4);
            const float2 f5 = __ldg(tl + id5);
            const float2 f6 = __ldg(tl + id6);
            const float2 f7 = __ldg(tl + id7);

            const float wx0 = 1.0f - wx, wy0 = 1.0f - wy, wz0 = 1.0f - wz;
            const float w00 = wy0 * wz0, w10 = wy * wz0, w01 = wy0 * wz, w11 = wy * wz;
            const float c0 = wx0 * w00, c1 = wx * w00;
            const float c2 = wx0 * w10, c3 = wx * w10;
            const float c4 = wx0 * w01, c5 = wx * w01;
            const float c6 = wx0 * w11, c7 = wx * w11;

            float e0 = f0.x * c0; float e1 = f0.y * c0;
            e0 = fmaf(f1.x, c1, e0); e1 = fmaf(f1.y, c1, e1);
            e0 = fmaf(f2.x, c2, e0); e1 = fmaf(f2.y, c2, e1);
            e0 = fmaf(f3.x, c3, e0); e1 = fmaf(f3.y, c3, e1);
            e0 = fmaf(f4.x, c4, e0); e1 = fmaf(f4.y, c4, e1);
            e0 = fmaf(f5.x, c5, e0); e1 = fmaf(f5.y, c5, e1);
            e0 = fmaf(f6.x, c6, e0); e1 = fmaf(f6.y, c6, e1);
            e0 = fmaf(f7.x, c7, e0); e1 = fmaf(f7.y, c7, e1);

            arow[2 * l + 0] = tf32r(e0);
            arow[2 * l + 1] = tf32r(e1);
        }
    }
    __syncwarp();

    // =============== sigma layer 1: [32x32] @ [32x64], relu ===============
    {
        const float* sW1 = sm + OFF_W1;
        unsigned a[2][4][4];
        load_a4(A, g, t, 0, a);
        __syncwarp();
        float acc[2][8][4];
        #pragma unroll
        for (int mt = 0; mt < 2; mt++)
        #pragma unroll
        for (int nt = 0; nt < 8; nt++)
        #pragma unroll
        for (int q = 0; q < 4; q++) acc[mt][nt][q] = 0.0f;

        #pragma unroll
        for (int nt = 0; nt < 8; nt++)
        #pragma unroll
        for (int kt = 0; kt < 4; kt++) {
            unsigned b[2];
            b[0] = __float_as_uint(sW1[(kt * 8 + t    ) * 72 + nt * 8 + g]);
            b[1] = __float_as_uint(sW1[(kt * 8 + t + 4) * 72 + nt * 8 + g]);
            mma8(acc[0][nt], a[0][kt], b);
            mma8(acc[1][nt], a[1][kt], b);
        }
        #pragma unroll
        for (int mt = 0; mt < 2; mt++)
        #pragma unroll
        for (int nt = 0; nt < 8; nt++) {
            const int r = mt * 16 + g, n = nt * 8 + 2 * t;
            A[(r    ) * ASTR + n    ] = tf32r(fmaxf(acc[mt][nt][0], 0.f));
            A[(r    ) * ASTR + n + 1] = tf32r(fmaxf(acc[mt][nt][1], 0.f));
            A[(r + 8) * ASTR + n    ] = tf32r(fmaxf(acc[mt][nt][2], 0.f));
            A[(r + 8) * ASTR + n + 1] = tf32r(fmaxf(acc[mt][nt][3], 0.f));
        }
    }
    __syncwarp();

    // =============== sigma layer 2: [32x64] @ [64x24], k in two halves ===============
    {
        const float* sW2 = sm + OFF_W2;
        float acc[2][3][4];
        #pragma unroll
        for (int mt = 0; mt < 2; mt++)
        #pragma unroll
        for (int nt = 0; nt < 3; nt++)
        #pragma unroll
        for (int q = 0; q < 4; q++) acc[mt][nt][q] = 0.0f;

        #pragma unroll
        for (int half = 0; half < 2; half++) {
            unsigned a[2][4][4];
            load_a4(A, g, t, half * 4, a);
            #pragma unroll
            for (int nt = 0; nt < 3; nt++)
            #pragma unroll
            for (int kk = 0; kk < 4; kk++) {
                const int kt = half * 4 + kk;
                unsigned b[2];
                b[0] = __float_as_uint(sW2[(kt * 8 + t    ) * 24 + nt * 8 + g]);
                b[1] = __float_as_uint(sW2[(kt * 8 + t + 4) * 24 + nt * 8 + g]);
                mma8(acc[0][nt], a[0][kk], b);
                mma8(acc[1][nt], a[1][kk], b);
            }
        }
        __syncwarp();   // all reads of h done before overwriting act

        // SH basis -> act cols 0..15 (own row)
        {
            const float dx = drx * 2.0f - 1.0f;
            const float dy = dry * 2.0f - 1.0f;
            const float dz = drz * 2.0f - 1.0f;
            const float x2 = dx * dx, y2 = dy * dy, z2 = dz * dz;
            const float xy = dx * dy, yz = dy * dz, xz = dx * dz;
            float* arow = A + ln * ASTR;
            arow[0]  = tf32r(0.28209479177387814f);
            arow[1]  = tf32r(-0.48860251190291987f * dy);
            arow[2]  = tf32r(0.48860251190291987f * dz);
            arow[3]  = tf32r(-0.48860251190291987f * dx);
            arow[4]  = tf32r(1.0925484305920792f * xy);
            arow[5]  = tf32r(-1.0925484305920792f * yz);
            arow[6]  = tf32r(0.94617469575756f * z2 - 0.31539156525252f);
            arow[7]  = tf32r(-1.0925484305920792f * xz);
            arow[8]  = tf32r(0.5462742152960396f * (x2 - y2));
            arow[9]  = tf32r(0.5900435899266435f * dy * (-3.0f * x2 + y2));
            arow[10] = tf32r(2.890611442640554f * xy * dz);
            arow[11] = tf32r(0.4570457994644657f * dy * (1.0f - 5.0f * z2));
            arow[12] = tf32r(0.3731763325901154f * dz * (5.0f * z2 - 3.0f));
            arow[13] = tf32r(0.4570457994644657f * dx * (1.0f - 5.0f * z2));
            arow[14] = tf32r(1.445305721320277f * dz * (x2 - y2));
            arow[15] = tf32r(0.5900435899266435f * dx * (-x2 + 3.0f * y2));
        }

        // sigma (col 0) -> global; geometry cols 1..16 -> act cols 16..31
        #pragma unroll
        for (int mt = 0; mt < 2; mt++) {
            const int r = mt * 16 + g;
            #pragma unroll
            for (int nt = 0; nt < 3; nt++) {
                const int n0 = nt * 8 + 2 * t;
                const float v0 = acc[mt][nt][0], v1 = acc[mt][nt][1];
                const float v2 = acc[mt][nt][2], v3 = acc[mt][nt][3];
                if (n0 == 0) {
                    const int p0 = base + r, p1 = base + r + 8;
                    if (p0 < N) out[(size_t)3 * N + p0] = fmaxf(v0, 0.f);
                    if (p1 < N) out[(size_t)3 * N + p1] = fmaxf(v2, 0.f);
                } else if (n0 >= 1 && n0 <= 16) {
                    A[(r    ) * ASTR + 15 + n0] = tf32r(v0);
                    A[(r + 8) * ASTR + 15 + n0] = tf32r(v2);
                }
                const int n1 = n0 + 1;
                if (n1 >= 1 && n1 <= 16) {
                    A[(r    ) * ASTR + 15 + n1] = tf32r(v1);
                    A[(r + 8) * ASTR + 15 + n1] = tf32r(v3);
                }
            }
        }
    }

    // -------- phase B staging: R1 overwrites sigma weights --------
    __syncthreads();
    {
        float* sR1w = sm + OFF_R1;
        for (int i = tid; i < 32 * 64; i += 128) { int r = i >> 6, c = i & 63; sR1w[r * 72 + c] = tf32r(wr1[i]); }
    }
    __syncthreads();

    // =============== rgb layer 1: [32x32] @ [32x64], relu ===============
    {
        const float* sR1 = sm + OFF_R1;
        unsigned a[2][4][4];
        load_a4(A, g, t, 0, a);
        __syncwarp();
        float acc[2][8][4];
        #pragma unroll
        for (int mt = 0; mt < 2; mt++)
        #pragma unroll
        for (int nt = 0; nt < 8; nt++)
        #pragma unroll
        for (int q = 0; q < 4; q++) acc[mt][nt][q] = 0.0f;

        #pragma unroll
        for (int nt = 0; nt < 8; nt++)
        #pragma unroll
        for (int kt = 0; kt < 4; kt++) {
            unsigned b[2];
            b[0] = __float_as_uint(sR1[(kt * 8 + t    ) * 72 + nt * 8 + g]);
            b[1] = __float_as_uint(sR1[(kt * 8 + t + 4) * 72 + nt * 8 + g]);
            mma8(acc[0][nt], a[0][kt], b);
            mma8(acc[1][nt], a[1][kt], b);
        }
        #pragma unroll
        for (int mt = 0; mt < 2; mt++)
        #pragma unroll
        for (int nt = 0; nt < 8; nt++) {
            const int r = mt * 16 + g, n = nt * 8 + 2 * t;
            A[(r    ) * ASTR + n    ] = tf32r(fmaxf(acc[mt][nt][0], 0.f));
            A[(r    ) * ASTR + n + 1] = tf32r(fmaxf(acc[mt][nt][1], 0.f));
            A[(r + 8) * ASTR + n    ] = tf32r(fmaxf(acc[mt][nt][2], 0.f));
            A[(r + 8) * ASTR + n + 1] = tf32r(fmaxf(acc[mt][nt][3], 0.f));
        }
    }

    // -------- phase C staging: R2,R3 overwrite R1 --------
    __syncthreads();
    {
        float* sR2w = sm + OFF_R2;
        float* sR3w = sm + OFF_R3;
        for (int i = tid; i < 64 * 64; i += 128) { int r = i >> 6, c = i & 63; sR2w[r * 72 + c] = tf32r(wr2[i]); }
        for (int i = tid; i < 64 * 8;  i += 128) {
            int r = i >> 3, c = i & 7;
            sR3w[i] = (c < 3) ? tf32r(wr3[r * 3 + c]) : 0.0f;
        }
    }
    __syncthreads();

    // =============== rgb layer 2: [32x64] @ [64x64], relu, k in two halves ===============
    {
        const float* sR2 = sm + OFF_R2;
        float acc[2][8][4];
        #pragma unroll
        for (int mt = 0; mt < 2; mt++)
        #pragma unroll
        for (int nt = 0; nt < 8; nt++)
        #pragma unroll
        for (int q = 0; q < 4; q++) acc[mt][nt][q] = 0.0f;

        #pragma unroll
        for (int half = 0; half < 2; half++) {
            unsigned a[2][4][4];
            load_a4(A, g, t, half * 4, a);
            #pragma unroll
            for (int nt = 0; nt < 8; nt++)
            #pragma unroll
            for (int kk = 0; kk < 4; kk++) {
                const int kt = half * 4 + kk;
                unsigned b[2];
                b[0] = __float_as_uint(sR2[(kt * 8 + t    ) * 72 + nt * 8 + g]);
                b[1] = __float_as_uint(sR2[(kt * 8 + t + 4) * 72 + nt * 8 + g]);
                mma8(acc[0][nt], a[0][kk], b);
                mma8(acc[1][nt], a[1][kk], b);
            }
        }
        __syncwarp();
        #pragma unroll
        for (int mt = 0; mt < 2; mt++)
        #pragma unroll
        for (int nt = 0; nt < 8; nt++) {
            const int r = mt * 16 + g, n = nt * 8 + 2 * t;
            A[(r    ) * ASTR + n    ] = tf32r(fmaxf(acc[mt][nt][0], 0.f));
            A[(r    ) * ASTR + n + 1] = tf32r(fmaxf(acc[mt][nt][1], 0.f));
            A[(r + 8) * ASTR + n    ] = tf32r(fmaxf(acc[mt][nt][2], 0.f));
            A[(r + 8) * ASTR + n + 1] = tf32r(fmaxf(acc[mt][nt][3], 0.f));
        }
    }
    __syncwarp();

    // =============== rgb layer 3: [32x64] @ [64x8] (cols 0..2 real), sigmoid ===============
    {
        const float* sR3 = sm + OFF_R3;
        float acc[2][4];
        #pragma unroll
        for (int mt = 0; mt < 2; mt++)
        #pragma unroll
        for (int q = 0; q < 4; q++) acc[mt][q] = 0.0f;

        #pragma unroll
        for (int half = 0; half < 2; half++) {
            unsigned a[2][4][4];
            load_a4(A, g, t, half * 4, a);
            #pragma unroll
            for (int kk = 0; kk < 4; kk++) {
                const int kt = half * 4 + kk;
                unsigned b[2];
                b[0] = __float_as_uint(sR3[(kt * 8 + t    ) * 8 + g]);
                b[1] = __float_as_uint(sR3[(kt * 8 + t + 4) * 8 + g]);
                mma8(acc[0], a[0][kk], b);
                mma8(acc[1], a[1][kk], b);
            }
        }
        const int n0 = 2 * t;
        #pragma unroll
        for (int mt = 0; mt < 2; mt++) {
            const int r = mt * 16 + g;
            const int p0 = base + r, p1 = base + r + 8;
            if (n0 < 3) {
                if (p0 < N) out[3 * p0 + n0] = 1.0f / (1.0f + __expf(-acc[mt][0]));
                if (p1 < N) out[3 * p1 + n0] = 1.0f / (1.0f + __expf(-acc[mt][2]));
            }
            if (n0 + 1 < 3) {
                if (p0 < N) out[3 * p0 + n0 + 1] = 1.0f / (1.0f + __expf(-acc[mt][1]));
                if (p1 < N) out[3 * p1 + n0 + 1] = 1.0f / (1.0f + __expf(-acc[mt][3]));
            }
        }
    }
}

extern "C" void kernel_launch(void* const* d_in, const int* in_sizes, int n_in,
                              void* d_out, int out_size)
{
    const float* xyz   = (const float*)d_in[0];
    const float* dirp  = (const float*)d_in[1];
    const float* table = (const float*)d_in[2];
    const float* w1    = (const float*)d_in[3];
    const float* w2    = (const float*)d_in[4];
    const float* wr1   = (const float*)d_in[5];
    const float* wr2   = (const float*)d_in[6];
    const float* wr3   = (const float*)d_in[7];
    float* out = (float*)d_out;

    static int smem_set = 0;
    const int smem_bytes = SMEM_FLOATS * sizeof(float);
    if (!smem_set) {
        cudaFuncSetAttribute(nerf_mma_kernel,
                             cudaFuncAttributeMaxDynamicSharedMemorySize, smem_bytes);
        smem_set = 1;
    }

    const int N = in_sizes[0] / 3;
    const int grid = (N + 127) / 128;
    nerf_mma_kernel<<<grid, 128, smem_bytes>>>(xyz, dirp, table, w1, w2, wr1, wr2, wr3, out, N);
}

// round 13
// speedup vs baseline: 1.2276x; 1.2276x over previous
#include <cuda_runtime.h>
#include <cuda_bf16.h>
#include <math.h>

#define NLEV 16
#define TBL (1u << 19)

// ---- dynamic shared layout (float units) ----
// Weight region PHASED 2 ways (R10-proven):
//   phase A: W1 [32][72]=2304 @0, W2 [64][24]=1536 @2304
//   phase B: R1 [32][72]=2304 @0, R2 [64][72]=4608 @2304, R3 [64][8]=512 @6912
#define OFF_W1 0
#define OFF_W2 2304
#define OFF_R1 0
#define OFF_R2 2304
#define OFF_R3 6912
#define WT_FLOATS 7424
#define OFF_ACT 7424        // 4 warps x [16][68] = 4352
#define SMEM_FLOATS 11776   // 47104 bytes
#define ASTR 68

__device__ __constant__ int c_res[16] = {16, 22, 30, 42, 58, 80, 111, 153,
                                         212, 294, 406, 561, 775, 1072, 1481, 2047};

__device__ __forceinline__ float tf32r(float x) {
    unsigned u;
    asm("cvt.rna.tf32.f32 %0, %1;" : "=r"(u) : "f"(x));
    return __uint_as_float(u);
}

__device__ __forceinline__ void mma8(float* c, const unsigned* a, const unsigned* b) {
    asm volatile(
        "mma.sync.aligned.m16n8k8.row.col.f32.tf32.tf32.f32 "
        "{%0,%1,%2,%3}, {%4,%5,%6,%7}, {%8,%9}, {%0,%1,%2,%3};\n"
        : "+f"(c[0]), "+f"(c[1]), "+f"(c[2]), "+f"(c[3])
        : "r"(a[0]), "r"(a[1]), "r"(a[2]), "r"(a[3]), "r"(b[0]), "r"(b[1]));
}

__global__ __launch_bounds__(128)
void nerf_mma_kernel(const float* __restrict__ xyz,
                     const float* __restrict__ dirp,
                     const float* __restrict__ table,
                     const float* __restrict__ w1,
                     const float* __restrict__ w2,
                     const float* __restrict__ wr1,
                     const float* __restrict__ wr2,
                     const float* __restrict__ wr3,
                     float* __restrict__ out, int N)
{
    extern __shared__ __align__(16) float sm[];
    const int tid = threadIdx.x;

    // -------- phase A staging: sigma weights --------
    {
        float* sW1 = sm + OFF_W1;
        float* sW2 = sm + OFF_W2;
        for (int i = tid; i < 32 * 64; i += 128) { int r = i >> 6, c = i & 63; sW1[r * 72 + c] = tf32r(w1[i]); }
        for (int i = tid; i < 64 * 24; i += 128) {
            int r = i / 24, c = i % 24;
            sW2[i] = (c < 17) ? tf32r(w2[r * 17 + c]) : 0.0f;
        }
    }
    __syncthreads();

    const int ln = tid & 31;
    const int wp = tid >> 5;
    const int g  = ln >> 2;      // group id (0..7)
    const int t  = ln & 3;       // thread-in-group (0..3)
    float* A = sm + OFF_ACT + wp * (16 * ASTR);

    const int base = blockIdx.x * 64 + wp * 16;   // 16 points per warp
    const int p    = ln & 15;                     // point handled in encode
    const int lo   = (ln >> 4) * 8;               // level half: 0..7 or 8..15
    const int idxp = base + p;
    const int pidx = idxp < N ? idxp : N - 1;

    // direction raw components (SH computed at write site, lanes 0..15 only)
    const float drx = dirp[3 * pidx + 0];
    const float dry = dirp[3 * pidx + 1];
    const float drz = dirp[3 * pidx + 2];

    // -------- hash-grid encode: 2 threads/point, 8 levels each --------
    {
        const float x = xyz[3 * pidx + 0];
        const float y = xyz[3 * pidx + 1];
        const float z = xyz[3 * pidx + 2];
        float* arow = A + p * ASTR;

        #pragma unroll
        for (int i = 0; i < 8; i++) {
            const int l = lo + i;
            const int res = c_res[l];
            const float rf = (float)res;
            const float px = x * rf, py = y * rf, pz = z * rf;
            const float fx = floorf(px), fy = floorf(py), fz = floorf(pz);
            const float wx = px - fx, wy = py - fy, wz = pz - fz;
            const unsigned X = (unsigned)fx, Y = (unsigned)fy, Z = (unsigned)fz;

            unsigned id0, id1, id2, id3, id4, id5, id6, id7;
            if (l < 5) {
                const unsigned s  = (unsigned)(res + 1);
                const unsigned s2 = s * s;
                const unsigned b0 = X + Y * s + Z * s2;
                id0 = b0;          id1 = b0 + 1u;
                id2 = b0 + s;      id3 = b0 + s + 1u;
                id4 = b0 + s2;     id5 = b0 + s2 + 1u;
                id6 = b0 + s2 + s; id7 = b0 + s2 + s + 1u;
            } else {
                const unsigned P1 = 2654435761u, P2 = 805459861u;
                const unsigned hx0 = X, hx1 = X + 1u;
                const unsigned hy0 = Y * P1, hy1 = (Y + 1u) * P1;
                const unsigned hz0 = Z * P2, hz1 = (Z + 1u) * P2;
                const unsigned M = TBL - 1u;
                id0 = (hx0 ^ hy0 ^ hz0) & M;  id1 = (hx1 ^ hy0 ^ hz0) & M;
                id2 = (hx0 ^ hy1 ^ hz0) & M;  id3 = (hx1 ^ hy1 ^ hz0) & M;
                id4 = (hx0 ^ hy0 ^ hz1) & M;  id5 = (hx1 ^ hy0 ^ hz1) & M;
                id6 = (hx0 ^ hy1 ^ hz1) & M;  id7 = (hx1 ^ hy1 ^ hz1) & M;
            }

            const float2* tl = (const float2*)table + (size_t)l * TBL;
            const float2 f0 = __ldg(tl + id0);
            const float2 f1 = __ldg(tl + id1);
            const float2 f2 = __ldg(tl + id2);
            const float2 f3 = __ldg(tl + id3);
            const float2 f4 = __ldg(tl + id4);
            const float2 f5 = __ldg(tl + id5);
            const float2 f6 = __ldg(tl + id6);
            const float2 f7 = __ldg(tl + id7);

            const float wx0 = 1.0f - wx, wy0 = 1.0f - wy, wz0 = 1.0f - wz;
            const float w00 = wy0 * wz0, w10 = wy * wz0, w01 = wy0 * wz, w11 = wy * wz;
            const float c0 = wx0 * w00, c1 = wx * w00;
            const float c2 = wx0 * w10, c3 = wx * w10;
            const float c4 = wx0 * w01, c5 = wx * w01;
            const float c6 = wx0 * w11, c7 = wx * w11;

            float e0 = f0.x * c0; float e1 = f0.y * c0;
            e0 = fmaf(f1.x, c1, e0); e1 = fmaf(f1.y, c1, e1);
            e0 = fmaf(f2.x, c2, e0); e1 = fmaf(f2.y, c2, e1);
            e0 = fmaf(f3.x, c3, e0); e1 = fmaf(f3.y, c3, e1);
            e0 = fmaf(f4.x, c4, e0); e1 = fmaf(f4.y, c4, e1);
            e0 = fmaf(f5.x, c5, e0); e1 = fmaf(f5.y, c5, e1);
            e0 = fmaf(f6.x, c6, e0); e1 = fmaf(f6.y, c6, e1);
            e0 = fmaf(f7.x, c7, e0); e1 = fmaf(f7.y, c7, e1);

            arow[2 * l + 0] = tf32r(e0);
            arow[2 * l + 1] = tf32r(e1);
        }
    }
    __syncwarp();

    // =============== sigma layer 1: [16x32] @ [32x64], relu ===============
    {
        const float* sW1 = sm + OFF_W1;
        unsigned a[4][4];
        #pragma unroll
        for (int kt = 0; kt < 4; kt++) {
            const int k = kt * 8 + t;
            a[kt][0] = __float_as_uint(A[(g    ) * ASTR + k    ]);
            a[kt][1] = __float_as_uint(A[(g + 8) * ASTR + k    ]);
            a[kt][2] = __float_as_uint(A[(g    ) * ASTR + k + 4]);
            a[kt][3] = __float_as_uint(A[(g + 8) * ASTR + k + 4]);
        }
        __syncwarp();
        float acc[8][4];
        #pragma unroll
        for (int nt = 0; nt < 8; nt++)
        #pragma unroll
        for (int q = 0; q < 4; q++) acc[nt][q] = 0.0f;

        #pragma unroll
        for (int nt = 0; nt < 8; nt++)
        #pragma unroll
        for (int kt = 0; kt < 4; kt++) {
            unsigned b[2];
            b[0] = __float_as_uint(sW1[(kt * 8 + t    ) * 72 + nt * 8 + g]);
            b[1] = __float_as_uint(sW1[(kt * 8 + t + 4) * 72 + nt * 8 + g]);
            mma8(acc[nt], a[kt], b);
        }
        #pragma unroll
        for (int nt = 0; nt < 8; nt++) {
            const int n = nt * 8 + 2 * t;
            A[(g    ) * ASTR + n    ] = tf32r(fmaxf(acc[nt][0], 0.f));
            A[(g    ) * ASTR + n + 1] = tf32r(fmaxf(acc[nt][1], 0.f));
            A[(g + 8) * ASTR + n    ] = tf32r(fmaxf(acc[nt][2], 0.f));
            A[(g + 8) * ASTR + n + 1] = tf32r(fmaxf(acc[nt][3], 0.f));
        }
    }
    __syncwarp();

    // =============== sigma layer 2: [16x64] @ [64x24] ===============
    {
        const float* sW2 = sm + OFF_W2;
        unsigned a[8][4];
        #pragma unroll
        for (int kt = 0; kt < 8; kt++) {
            const int k = kt * 8 + t;
            a[kt][0] = __float_as_uint(A[(g    ) * ASTR + k    ]);
            a[kt][1] = __float_as_uint(A[(g + 8) * ASTR + k    ]);
            a[kt][2] = __float_as_uint(A[(g    ) * ASTR + k + 4]);
            a[kt][3] = __float_as_uint(A[(g + 8) * ASTR + k + 4]);
        }
        __syncwarp();   // reads of h done before overwriting act

        float acc[3][4];
        #pragma unroll
        for (int nt = 0; nt < 3; nt++)
        #pragma unroll
        for (int q = 0; q < 4; q++) acc[nt][q] = 0.0f;

        #pragma unroll
        for (int nt = 0; nt < 3; nt++)
        #pragma unroll
        for (int kt = 0; kt < 8; kt++) {
            unsigned b[2];
            b[0] = __float_as_uint(sW2[(kt * 8 + t    ) * 24 + nt * 8 + g]);
            b[1] = __float_as_uint(sW2[(kt * 8 + t + 4) * 24 + nt * 8 + g]);
            mma8(acc[nt], a[kt], b);
        }

        // SH basis -> act cols 0..15 (lanes 0..15 own one point each)
        if (ln < 16) {
            const float dx = drx * 2.0f - 1.0f;
            const float dy = dry * 2.0f - 1.0f;
            const float dz = drz * 2.0f - 1.0f;
            const float x2 = dx * dx, y2 = dy * dy, z2 = dz * dz;
            const float xy = dx * dy, yz = dy * dz, xz = dx * dz;
            float* arow = A + p * ASTR;
            arow[0]  = tf32r(0.28209479177387814f);
            arow[1]  = tf32r(-0.48860251190291987f * dy);
            arow[2]  = tf32r(0.48860251190291987f * dz);
            arow[3]  = tf32r(-0.48860251190291987f * dx);
            arow[4]  = tf32r(1.0925484305920792f * xy);
            arow[5]  = tf32r(-1.0925484305920792f * yz);
            arow[6]  = tf32r(0.94617469575756f * z2 - 0.31539156525252f);
            arow[7]  = tf32r(-1.0925484305920792f * xz);
            arow[8]  = tf32r(0.5462742152960396f * (x2 - y2));
            arow[9]  = tf32r(0.5900435899266435f * dy * (-3.0f * x2 + y2));
            arow[10] = tf32r(2.890611442640554f * xy * dz);
            arow[11] = tf32r(0.4570457994644657f * dy * (1.0f - 5.0f * z2));
            arow[12] = tf32r(0.3731763325901154f * dz * (5.0f * z2 - 3.0f));
            arow[13] = tf32r(0.4570457994644657f * dx * (1.0f - 5.0f * z2));
            arow[14] = tf32r(1.445305721320277f * dz * (x2 - y2));
            arow[15] = tf32r(0.5900435899266435f * dx * (-x2 + 3.0f * y2));
        }

        // sigma (col 0) -> global; geometry cols 1..16 -> act cols 16..31
        #pragma unroll
        for (int nt = 0; nt < 3; nt++) {
            const int n0 = nt * 8 + 2 * t;
            const float v0 = acc[nt][0], v1 = acc[nt][1];
            const float v2 = acc[nt][2], v3 = acc[nt][3];
            if (n0 == 0) {
                const int p0 = base + g, p1 = base + g + 8;
                if (p0 < N) out[(size_t)3 * N + p0] = fmaxf(v0, 0.f);
                if (p1 < N) out[(size_t)3 * N + p1] = fmaxf(v2, 0.f);
            } else if (n0 >= 1 && n0 <= 16) {
                A[(g    ) * ASTR + 15 + n0] = tf32r(v0);
                A[(g + 8) * ASTR + 15 + n0] = tf32r(v2);
            }
            const int n1 = n0 + 1;
            if (n1 >= 1 && n1 <= 16) {
                A[(g    ) * ASTR + 15 + n1] = tf32r(v1);
                A[(g + 8) * ASTR + 15 + n1] = tf32r(v3);
            }
        }
    }

    // -------- phase B staging: rgb weights overwrite sigma weights --------
    __syncthreads();
    {
        float* sR1w = sm + OFF_R1;
        float* sR2w = sm + OFF_R2;
        float* sR3w = sm + OFF_R3;
        for (int i = tid; i < 32 * 64; i += 128) { int r = i >> 6, c = i & 63; sR1w[r * 72 + c] = tf32r(wr1[i]); }
        for (int i = tid; i < 64 * 64; i += 128) { int r = i >> 6, c = i & 63; sR2w[r * 72 + c] = tf32r(wr2[i]); }
        for (int i = tid; i < 64 * 8;  i += 128) {
            int r = i >> 3, c = i & 7;
            sR3w[i] = (c < 3) ? tf32r(wr3[r * 3 + c]) : 0.0f;
        }
    }
    __syncthreads();

    // =============== rgb layer 1: [16x32] @ [32x64], relu ===============
    {
        const float* sR1 = sm + OFF_R1;
        unsigned a[4][4];
        #pragma unroll
        for (int kt = 0; kt < 4; kt++) {
            const int k = kt * 8 + t;
            a[kt][0] = __float_as_uint(A[(g    ) * ASTR + k    ]);
            a[kt][1] = __float_as_uint(A[(g + 8) * ASTR + k    ]);
            a[kt][2] = __float_as_uint(A[(g    ) * ASTR + k + 4]);
            a[kt][3] = __float_as_uint(A[(g + 8) * ASTR + k + 4]);
        }
        __syncwarp();
        float acc[8][4];
        #pragma unroll
        for (int nt = 0; nt < 8; nt++)
        #pragma unroll
        for (int q = 0; q < 4; q++) acc[nt][q] = 0.0f;

        #pragma unroll
        for (int nt = 0; nt < 8; nt++)
        #pragma unroll
        for (int kt = 0; kt < 4; kt++) {
            unsigned b[2];
            b[0] = __float_as_uint(sR1[(kt * 8 + t    ) * 72 + nt * 8 + g]);
            b[1] = __float_as_uint(sR1[(kt * 8 + t + 4) * 72 + nt * 8 + g]);
            mma8(acc[nt], a[kt], b);
        }
        #pragma unroll
        for (int nt = 0; nt < 8; nt++) {
            const int n = nt * 8 + 2 * t;
            A[(g    ) * ASTR + n    ] = tf32r(fmaxf(acc[nt][0], 0.f));
            A[(g    ) * ASTR + n + 1] = tf32r(fmaxf(acc[nt][1], 0.f));
            A[(g + 8) * ASTR + n    ] = tf32r(fmaxf(acc[nt][2], 0.f));
            A[(g + 8) * ASTR + n + 1] = tf32r(fmaxf(acc[nt][3], 0.f));
        }
    }
    __syncwarp();

    // =============== rgb layer 2: [16x64] @ [64x64], relu ===============
    {
        const float* sR2 = sm + OFF_R2;
        unsigned a[8][4];
        #pragma unroll
        for (int kt = 0; kt < 8; kt++) {
            const int k = kt * 8 + t;
            a[kt][0] = __float_as_uint(A[(g    ) * ASTR + k    ]);
            a[kt][1] = __float_as_uint(A[(g + 8) * ASTR + k    ]);
            a[kt][2] = __float_as_uint(A[(g    ) * ASTR + k + 4]);
            a[kt][3] = __float_as_uint(A[(g + 8) * ASTR + k + 4]);
        }
        __syncwarp();
        float acc[8][4];
        #pragma unroll
        for (int nt = 0; nt < 8; nt++)
        #pragma unroll
        for (int q = 0; q < 4; q++) acc[nt][q] = 0.0f;

        #pragma unroll
        for (int nt = 0; nt < 8; nt++)
        #pragma unroll
        for (int kt = 0; kt < 8; kt++) {
            unsigned b[2];
            b[0] = __float_as_uint(sR2[(kt * 8 + t    ) * 72 + nt * 8 + g]);
            b[1] = __float_as_uint(sR2[(kt * 8 + t + 4) * 72 + nt * 8 + g]);
            mma8(acc[nt], a[kt], b);
        }
        #pragma unroll
        for (int nt = 0; nt < 8; nt++) {
            const int n = nt * 8 + 2 * t;
            A[(g    ) * ASTR + n    ] = tf32r(fmaxf(acc[nt][0], 0.f));
            A[(g    ) * ASTR + n + 1] = tf32r(fmaxf(acc[nt][1], 0.f));
            A[(g + 8) * ASTR + n    ] = tf32r(fmaxf(acc[nt][2], 0.f));
            A[(g + 8) * ASTR + n + 1] = tf32r(fmaxf(acc[nt][3], 0.f));
        }
    }
    __syncwarp();

    // =============== rgb layer 3: [16x64] @ [64x8] (cols 0..2 real), sigmoid ===============
    {
        const float* sR3 = sm + OFF_R3;
        unsigned a[8][4];
        #pragma unroll
        for (int kt = 0; kt < 8; kt++) {
            const int k = kt * 8 + t;
            a[kt][0] = __float_as_uint(A[(g    ) * ASTR + k    ]);
            a[kt][1] = __float_as_uint(A[(g + 8) * ASTR + k    ]);
            a[kt][2] = __float_as_uint(A[(g    ) * ASTR + k + 4]);
            a[kt][3] = __float_as_uint(A[(g + 8) * ASTR + k + 4]);
        }
        float acc[4];
        #pragma unroll
        for (int q = 0; q < 4; q++) acc[q] = 0.0f;

        #pragma unroll
        for (int kt = 0; kt < 8; kt++) {
            unsigned b[2];
            b[0] = __float_as_uint(sR3[(kt * 8 + t    ) * 8 + g]);
            b[1] = __float_as_uint(sR3[(kt * 8 + t + 4) * 8 + g]);
            mma8(acc, a[kt], b);
        }
        const int n0 = 2 * t;
        const int p0 = base + g, p1 = base + g + 8;
        if (n0 < 3) {
            if (p0 < N) out[3 * p0 + n0] = 1.0f / (1.0f + __expf(-acc[0]));
            if (p1 < N) out[3 * p1 + n0] = 1.0f / (1.0f + __expf(-acc[2]));
        }
        if (n0 + 1 < 3) {
            if (p0 < N) out[3 * p0 + n0 + 1] = 1.0f / (1.0f + __expf(-acc[1]));
            if (p1 < N) out[3 * p1 + n0 + 1] = 1.0f / (1.0f + __expf(-acc[3]));
        }
    }
}

extern "C" void kernel_launch(void* const* d_in, const int* in_sizes, int n_in,
                              void* d_out, int out_size)
{
    const float* xyz   = (const float*)d_in[0];
    const float* dirp  = (const float*)d_in[1];
    const float* table = (const float*)d_in[2];
    const float* w1    = (const float*)d_in[3];
    const float* w2    = (const float*)d_in[4];
    const float* wr1   = (const float*)d_in[5];
    const float* wr2   = (const float*)d_in[6];
    const float* wr3   = (const float*)d_in[7];
    float* out = (float*)d_out;

    static int smem_set = 0;
    const int smem_bytes = SMEM_FLOATS * sizeof(float);
    if (!smem_set) {
        cudaFuncSetAttribute(nerf_mma_kernel,
                             cudaFuncAttributeMaxDynamicSharedMemorySize, smem_bytes);
        smem_set = 1;
    }

    const int N = in_sizes[0] / 3;
    const int grid = (N + 63) / 64;
    nerf_mma_kernel<<<grid, 128, smem_bytes>>>(xyz, dirp, table, w1, w2, wr1, wr2, wr3, out, N);
}

// round 14
// speedup vs baseline: 1.2365x; 1.0072x over previous
#include <cuda_runtime.h>
#include <cuda_bf16.h>
#include <math.h>

#define NLEV 16
#define TBL (1u << 19)

// ---- dense-level pair table: P[i] = (T[i], T[i+1]) as float4, per level ----
// sizes (res+1)^3 for res in {16,22,30,42,58}
#define PAIR_TOTAL 331757
__device__ float4 g_pair[PAIR_TOTAL];
__device__ __constant__ unsigned c_poff[5] = {0u, 4913u, 17080u, 46871u, 126378u};

// ---- dynamic shared layout (float units) ----
// Weight region is PHASED: sigma weights (W1,W2) first, then rgb weights
// (R1,R2,R3) re-staged into the same region behind a __syncthreads().
#define OFF_W1 0            // phase A: [32][72] = 2304
#define OFF_W2 2304         // phase A: [64][24] = 1536 (N=17 padded to 24)
#define OFF_R1 0            // phase B: [32][72] = 2304
#define OFF_R2 2304         // phase B: [64][72] = 4608
#define OFF_R3 6912         // phase B: [64][8]  = 512  (N=3 padded to 8)
#define OFF_ACT 7424        // 4 warps x [32][68] = 8704
#define SMEM_FLOATS 16128   // 64512 bytes -> 3 CTAs/SM
#define ASTR 68

__device__ __constant__ int c_res[16] = {16, 22, 30, 42, 58, 80, 111, 153,
                                         212, 294, 406, 561, 775, 1072, 1481, 2047};

__device__ __forceinline__ float tf32r(float x) {
    unsigned u;
    asm("cvt.rna.tf32.f32 %0, %1;" : "=r"(u) : "f"(x));
    return __uint_as_float(u);
}

__device__ __forceinline__ void mma8(float* c, const unsigned* a, const unsigned* b) {
    asm volatile(
        "mma.sync.aligned.m16n8k8.row.col.f32.tf32.tf32.f32 "
        "{%0,%1,%2,%3}, {%4,%5,%6,%7}, {%8,%9}, {%0,%1,%2,%3};\n"
        : "+f"(c[0]), "+f"(c[1]), "+f"(c[2]), "+f"(c[3])
        : "r"(a[0]), "r"(a[1]), "r"(a[2]), "r"(a[3]), "r"(b[0]), "r"(b[1]));
}

// ================= prep: build dense pair tables (runs each launch, ~10us) =================
__global__ __launch_bounds__(256)
void build_pair_kernel(const float* __restrict__ table)
{
    const int i = blockIdx.x * 256 + threadIdx.x;
    if (i >= PAIR_TOTAL) return;
    int l, off;
    if      (i >= 126378) { l = 4; off = 126378; }
    else if (i >= 46871)  { l = 3; off = 46871; }
    else if (i >= 17080)  { l = 2; off = 17080; }
    else if (i >= 4913)   { l = 1; off = 4913; }
    else                  { l = 0; off = 0; }
    const int j = i - off;
    const float2* T2 = (const float2*)table + (size_t)l * TBL;
    const float2 a = T2[j];
    const float2 b = T2[j + 1];   // stays within the level's TBL slab
    g_pair[i] = make_float4(a.x, a.y, b.x, b.y);
}

__global__ __launch_bounds__(128)
void nerf_mma_kernel(const float* __restrict__ xyz,
                     const float* __restrict__ dirp,
                     const float* __restrict__ table,
                     const float* __restrict__ w1,
                     const float* __restrict__ w2,
                     const float* __restrict__ wr1,
                     const float* __restrict__ wr2,
                     const float* __restrict__ wr3,
                     float* __restrict__ out, int N)
{
    extern __shared__ __align__(16) float sm[];
    float* sW1 = sm + OFF_W1;
    float* sW2 = sm + OFF_W2;

    const int tid = threadIdx.x;

    // -------- phase A staging: sigma weights only --------
    for (int i = tid; i < 32 * 64; i += 128) { int r = i >> 6, c = i & 63; sW1[r * 72 + c] = tf32r(w1[i]); }
    for (int i = tid; i < 64 * 24; i += 128) {
        int r = i / 24, c = i % 24;
        sW2[i] = (c < 17) ? tf32r(w2[r * 17 + c]) : 0.0f;
    }
    __syncthreads();

    const int ln = tid & 31;
    const int wp = tid >> 5;
    const int g  = ln >> 2;      // group id (0..7)
    const int t  = ln & 3;       // thread-in-group (0..3)
    float* A = sm + OFF_ACT + wp * (32 * ASTR);

    const int base = blockIdx.x * 128 + wp * 32;   // first point of this warp's tile
    const int idx  = base + ln;
    const int pidx = idx < N ? idx : N - 1;

    // -------- direction load + SH basis (compute early, keep in regs) --------
    float sh[16];
    {
        const float dx = dirp[3 * pidx + 0] * 2.0f - 1.0f;
        const float dy = dirp[3 * pidx + 1] * 2.0f - 1.0f;
        const float dz = dirp[3 * pidx + 2] * 2.0f - 1.0f;
        const float x2 = dx * dx, y2 = dy * dy, z2 = dz * dz;
        const float xy = dx * dy, yz = dy * dz, xz = dx * dz;
        sh[0]  = 0.28209479177387814f;
        sh[1]  = -0.48860251190291987f * dy;
        sh[2]  = 0.48860251190291987f * dz;
        sh[3]  = -0.48860251190291987f * dx;
        sh[4]  = 1.0925484305920792f * xy;
        sh[5]  = -1.0925484305920792f * yz;
        sh[6]  = 0.94617469575756f * z2 - 0.31539156525252f;
        sh[7]  = -1.0925484305920792f * xz;
        sh[8]  = 0.5462742152960396f * (x2 - y2);
        sh[9]  = 0.5900435899266435f * dy * (-3.0f * x2 + y2);
        sh[10] = 2.890611442640554f * xy * dz;
        sh[11] = 0.4570457994644657f * dy * (1.0f - 5.0f * z2);
        sh[12] = 0.3731763325901154f * dz * (5.0f * z2 - 3.0f);
        sh[13] = 0.4570457994644657f * dx * (1.0f - 5.0f * z2);
        sh[14] = 1.445305721320277f * dz * (x2 - y2);
        sh[15] = 0.5900435899266435f * dx * (-x2 + 3.0f * y2);
    }

    // -------- hash-grid encode -> act row ln, cols 0..31 (tf32-rounded) --------
    {
        const float x = xyz[3 * pidx + 0];
        const float y = xyz[3 * pidx + 1];
        const float z = xyz[3 * pidx + 2];
        float* arow = A + ln * ASTR;

        // dense levels 0..4: x-corner pairs merged via pair table (4x LDG.128)
        #pragma unroll
        for (int l = 0; l < 5; l++) {
            const int res = c_res[l];
            const float rf = (float)res;
            const float px = x * rf, py = y * rf, pz = z * rf;
            const float fx = floorf(px), fy = floorf(py), fz = floorf(pz);
            const float wx = px - fx, wy = py - fy, wz = pz - fz;
            const unsigned X = (unsigned)fx, Y = (unsigned)fy, Z = (unsigned)fz;

            const unsigned s  = (unsigned)(res + 1);
            const unsigned s2 = s * s;
            const unsigned b0 = X + Y * s + Z * s2;

            const float4* P = g_pair + c_poff[l];
            const float4 q0 = __ldg(P + b0);            // corners (c0, c1)
            const float4 q1 = __ldg(P + b0 + s);        // corners (c2, c3)
            const float4 q2 = __ldg(P + b0 + s2);       // corners (c4, c5)
            const float4 q3 = __ldg(P + b0 + s2 + s);   // corners (c6, c7)

            const float wx0 = 1.0f - wx, wy0 = 1.0f - wy, wz0 = 1.0f - wz;
            const float w00 = wy0 * wz0, w10 = wy * wz0, w01 = wy0 * wz, w11 = wy * wz;
            const float c0 = wx0 * w00, c1 = wx * w00;
            const float c2 = wx0 * w10, c3 = wx * w10;
            const float c4 = wx0 * w01, c5 = wx * w01;
            const float c6 = wx0 * w11, c7 = wx * w11;

            float e0 = q0.x * c0; float e1 = q0.y * c0;
            e0 = fmaf(q0.z, c1, e0); e1 = fmaf(q0.w, c1, e1);
            e0 = fmaf(q1.x, c2, e0); e1 = fmaf(q1.y, c2, e1);
            e0 = fmaf(q1.z, c3, e0); e1 = fmaf(q1.w, c3, e1);
            e0 = fmaf(q2.x, c4, e0); e1 = fmaf(q2.y, c4, e1);
            e0 = fmaf(q2.z, c5, e0); e1 = fmaf(q2.w, c5, e1);
            e0 = fmaf(q3.x, c6, e0); e1 = fmaf(q3.y, c6, e1);
            e0 = fmaf(q3.z, c7, e0); e1 = fmaf(q3.w, c7, e1);

            arow[2 * l + 0] = tf32r(e0);
            arow[2 * l + 1] = tf32r(e1);
        }

        // hashed levels 5..15
        #pragma unroll
        for (int l = 5; l < NLEV; l++) {
            const int res = c_res[l];
            const float rf = (float)res;
            const float px = x * rf, py = y * rf, pz = z * rf;
            const float fx = floorf(px), fy = floorf(py), fz = floorf(pz);
            const float wx = px - fx, wy = py - fy, wz = pz - fz;
            const unsigned X = (unsigned)fx, Y = (unsigned)fy, Z = (unsigned)fz;

            const unsigned P1 = 2654435761u, P2 = 805459861u;
            const unsigned hx0 = X, hx1 = X + 1u;
            const unsigned hy0 = Y * P1, hy1 = (Y + 1u) * P1;
            const unsigned hz0 = Z * P2, hz1 = (Z + 1u) * P2;
            const unsigned M = TBL - 1u;
            const unsigned id0 = (hx0 ^ hy0 ^ hz0) & M;  const unsigned id1 = (hx1 ^ hy0 ^ hz0) & M;
            const unsigned id2 = (hx0 ^ hy1 ^ hz0) & M;  const unsigned id3 = (hx1 ^ hy1 ^ hz0) & M;
            const unsigned id4 = (hx0 ^ hy0 ^ hz1) & M;  const unsigned id5 = (hx1 ^ hy0 ^ hz1) & M;
            const unsigned id6 = (hx0 ^ hy1 ^ hz1) & M;  const unsigned id7 = (hx1 ^ hy1 ^ hz1) & M;

            const float2* tl = (const float2*)table + (size_t)l * TBL;
            const float2 f0 = __ldg(tl + id0);
            const float2 f1 = __ldg(tl + id1);
            const float2 f2 = __ldg(tl + id2);
            const float2 f3 = __ldg(tl + id3);
            const float2 f4 = __ldg(tl + id4);
            const float2 f5 = __ldg(tl + id5);
            const float2 f6 = __ldg(tl + id6);
            const float2 f7 = __ldg(tl + id7);

            const float wx0 = 1.0f - wx, wy0 = 1.0f - wy, wz0 = 1.0f - wz;
            const float w00 = wy0 * wz0, w10 = wy * wz0, w01 = wy0 * wz, w11 = wy * wz;
            const float c0 = wx0 * w00, c1 = wx * w00;
            const float c2 = wx0 * w10, c3 = wx * w10;
            const float c4 = wx0 * w01, c5 = wx * w01;
            const float c6 = wx0 * w11, c7 = wx * w11;

            float e0 = f0.x * c0; float e1 = f0.y * c0;
            e0 = fmaf(f1.x, c1, e0); e1 = fmaf(f1.y, c1, e1);
            e0 = fmaf(f2.x, c2, e0); e1 = fmaf(f2.y, c2, e1);
            e0 = fmaf(f3.x, c3, e0); e1 = fmaf(f3.y, c3, e1);
            e0 = fmaf(f4.x, c4, e0); e1 = fmaf(f4.y, c4, e1);
            e0 = fmaf(f5.x, c5, e0); e1 = fmaf(f5.y, c5, e1);
            e0 = fmaf(f6.x, c6, e0); e1 = fmaf(f6.y, c6, e1);
            e0 = fmaf(f7.x, c7, e0); e1 = fmaf(f7.y, c7, e1);

            arow[2 * l + 0] = tf32r(e0);
            arow[2 * l + 1] = tf32r(e1);
        }
    }
    __syncwarp();

    // =============== sigma layer 1: [32x32] @ [32x64], relu ===============
    {
        unsigned a[2][4][4];
        #pragma unroll
        for (int mt = 0; mt < 2; mt++)
        #pragma unroll
        for (int kt = 0; kt < 4; kt++) {
            const int r = mt * 16 + g, k = kt * 8 + t;
            a[mt][kt][0] = __float_as_uint(A[(r    ) * ASTR + k    ]);
            a[mt][kt][1] = __float_as_uint(A[(r + 8) * ASTR + k    ]);
            a[mt][kt][2] = __float_as_uint(A[(r    ) * ASTR + k + 4]);
            a[mt][kt][3] = __float_as_uint(A[(r + 8) * ASTR + k + 4]);
        }
        __syncwarp();
        float acc[2][8][4];
        #pragma unroll
        for (int mt = 0; mt < 2; mt++)
        #pragma unroll
        for (int nt = 0; nt < 8; nt++)
        #pragma unroll
        for (int q = 0; q < 4; q++) acc[mt][nt][q] = 0.0f;

        #pragma unroll
        for (int nt = 0; nt < 8; nt++)
        #pragma unroll
        for (int kt = 0; kt < 4; kt++) {
            unsigned b[2];
            b[0] = __float_as_uint(sW1[(kt * 8 + t    ) * 72 + nt * 8 + g]);
            b[1] = __float_as_uint(sW1[(kt * 8 + t + 4) * 72 + nt * 8 + g]);
            mma8(acc[0][nt], a[0][kt], b);
            mma8(acc[1][nt], a[1][kt], b);
        }
        #pragma unroll
        for (int mt = 0; mt < 2; mt++)
        #pragma unroll
        for (int nt = 0; nt < 8; nt++) {
            const int r = mt * 16 + g, n = nt * 8 + 2 * t;
            A[(r    ) * ASTR + n    ] = tf32r(fmaxf(acc[mt][nt][0], 0.f));
            A[(r    ) * ASTR + n + 1] = tf32r(fmaxf(acc[mt][nt][1], 0.f));
            A[(r + 8) * ASTR + n    ] = tf32r(fmaxf(acc[mt][nt][2], 0.f));
            A[(r + 8) * ASTR + n + 1] = tf32r(fmaxf(acc[mt][nt][3], 0.f));
        }
    }
    __syncwarp();

    // =============== sigma layer 2: [32x64] @ [64x24], no activation ===============
    {
        unsigned a[2][8][4];
        #pragma unroll
        for (int mt = 0; mt < 2; mt++)
        #pragma unroll
        for (int kt = 0; kt < 8; kt++) {
            const int r = mt * 16 + g, k = kt * 8 + t;
            a[mt][kt][0] = __float_as_uint(A[(r    ) * ASTR + k    ]);
            a[mt][kt][1] = __float_as_uint(A[(r + 8) * ASTR + k    ]);
            a[mt][kt][2] = __float_as_uint(A[(r    ) * ASTR + k + 4]);
            a[mt][kt][3] = __float_as_uint(A[(r + 8) * ASTR + k + 4]);
        }
        __syncwarp();   // everyone finished reading h before we overwrite act

        float acc[2][3][4];
        #pragma unroll
        for (int mt = 0; mt < 2; mt++)
        #pragma unroll
        for (int nt = 0; nt < 3; nt++)
        #pragma unroll
        for (int q = 0; q < 4; q++) acc[mt][nt][q] = 0.0f;

        #pragma unroll
        for (int nt = 0; nt < 3; nt++)
        #pragma unroll
        for (int kt = 0; kt < 8; kt++) {
            unsigned b[2];
            b[0] = __float_as_uint(sW2[(kt * 8 + t    ) * 24 + nt * 8 + g]);
            b[1] = __float_as_uint(sW2[(kt * 8 + t + 4) * 24 + nt * 8 + g]);
            mma8(acc[0][nt], a[0][kt], b);
            mma8(acc[1][nt], a[1][kt], b);
        }

        // SH basis -> act cols 0..15 (own row)
        #pragma unroll
        for (int i = 0; i < 16; i++) A[ln * ASTR + i] = tf32r(sh[i]);

        // sigma (col 0) -> global; geometry cols 1..16 -> act cols 16..31
        #pragma unroll
        for (int mt = 0; mt < 2; mt++) {
            const int r = mt * 16 + g;
            #pragma unroll
            for (int nt = 0; nt < 3; nt++) {
                const int n0 = nt * 8 + 2 * t;
                const float v0 = acc[mt][nt][0], v1 = acc[mt][nt][1];
                const float v2 = acc[mt][nt][2], v3 = acc[mt][nt][3];
                if (n0 == 0) {
                    const int p0 = base + r, p1 = base + r + 8;
                    if (p0 < N) out[(size_t)3 * N + p0] = fmaxf(v0, 0.f);
                    if (p1 < N) out[(size_t)3 * N + p1] = fmaxf(v2, 0.f);
                } else if (n0 >= 1 && n0 <= 16) {
                    A[(r    ) * ASTR + 15 + n0] = tf32r(v0);
                    A[(r + 8) * ASTR + 15 + n0] = tf32r(v2);
                }
                const int n1 = n0 + 1;
                if (n1 >= 1 && n1 <= 16) {
                    A[(r    ) * ASTR + 15 + n1] = tf32r(v1);
                    A[(r + 8) * ASTR + 15 + n1] = tf32r(v3);
                }
            }
        }
    }

    // -------- phase B staging: rgb weights overwrite sigma weights --------
    __syncthreads();   // all warps done reading sW1/sW2
    {
        float* sR1w = sm + OFF_R1;
        float* sR2w = sm + OFF_R2;
        float* sR3w = sm + OFF_R3;
        for (int i = tid; i < 32 * 64; i += 128) { int r = i >> 6, c = i & 63; sR1w[r * 72 + c] = tf32r(wr1[i]); }
        for (int i = tid; i < 64 * 64; i += 128) { int r = i >> 6, c = i & 63; sR2w[r * 72 + c] = tf32r(wr2[i]); }
        for (int i = tid; i < 64 * 8;  i += 128) {
            int r = i >> 3, c = i & 7;
            sR3w[i] = (c < 3) ? tf32r(wr3[r * 3 + c]) : 0.0f;
        }
    }
    __syncthreads();
    const float* sR1 = sm + OFF_R1;
    const float* sR2 = sm + OFF_R2;
    const float* sR3 = sm + OFF_R3;

    // =============== rgb layer 1: [32x32] @ [32x64], relu ===============
    {
        unsigned a[2][4][4];
        #pragma unroll
        for (int mt = 0; mt < 2; mt++)
        #pragma unroll
        for (int kt = 0; kt < 4; kt++) {
            const int r = mt * 16 + g, k = kt * 8 + t;
            a[mt][kt][0] = __float_as_uint(A[(r    ) * ASTR + k    ]);
            a[mt][kt][1] = __float_as_uint(A[(r + 8) * ASTR + k    ]);
            a[mt][kt][2] = __float_as_uint(A[(r    ) * ASTR + k + 4]);
            a[mt][kt][3] = __float_as_uint(A[(r + 8) * ASTR + k + 4]);
        }
        __syncwarp();
        float acc[2][8][4];
        #pragma unroll
        for (int mt = 0; mt < 2; mt++)
        #pragma unroll
        for (int nt = 0; nt < 8; nt++)
        #pragma unroll
        for (int q = 0; q < 4; q++) acc[mt][nt][q] = 0.0f;

        #pragma unroll
        for (int nt = 0; nt < 8; nt++)
        #pragma unroll
        for (int kt = 0; kt < 4; kt++) {
            unsigned b[2];
            b[0] = __float_as_uint(sR1[(kt * 8 + t    ) * 72 + nt * 8 + g]);
            b[1] = __float_as_uint(sR1[(kt * 8 + t + 4) * 72 + nt * 8 + g]);
            mma8(acc[0][nt], a[0][kt], b);
            mma8(acc[1][nt], a[1][kt], b);
        }
        #pragma unroll
        for (int mt = 0; mt < 2; mt++)
        #pragma unroll
        for (int nt = 0; nt < 8; nt++) {
            const int r = mt * 16 + g, n = nt * 8 + 2 * t;
            A[(r    ) * ASTR + n    ] = tf32r(fmaxf(acc[mt][nt][0], 0.f));
            A[(r    ) * ASTR + n + 1] = tf32r(fmaxf(acc[mt][nt][1], 0.f));
            A[(r + 8) * ASTR + n    ] = tf32r(fmaxf(acc[mt][nt][2], 0.f));
            A[(r + 8) * ASTR + n + 1] = tf32r(fmaxf(acc[mt][nt][3], 0.f));
        }
    }
    __syncwarp();

    // =============== rgb layer 2: [32x64] @ [64x64], relu ===============
    {
        unsigned a[2][8][4];
        #pragma unroll
        for (int mt = 0; mt < 2; mt++)
        #pragma unroll
        for (int kt = 0; kt < 8; kt++) {
            const int r = mt * 16 + g, k = kt * 8 + t;
            a[mt][kt][0] = __float_as_uint(A[(r    ) * ASTR + k    ]);
            a[mt][kt][1] = __float_as_uint(A[(r + 8) * ASTR + k    ]);
            a[mt][kt][2] = __float_as_uint(A[(r    ) * ASTR + k + 4]);
            a[mt][kt][3] = __float_as_uint(A[(r + 8) * ASTR + k + 4]);
        }
        __syncwarp();
        float acc[2][8][4];
        #pragma unroll
        for (int mt = 0; mt < 2; mt++)
        #pragma unroll
        for (int nt = 0; nt < 8; nt++)
        #pragma unroll
        for (int q = 0; q < 4; q++) acc[mt][nt][q] = 0.0f;

        #pragma unroll
        for (int nt = 0; nt < 8; nt++)
        #pragma unroll
        for (int kt = 0; kt < 8; kt++) {
            unsigned b[2];
            b[0] = __float_as_uint(sR2[(kt * 8 + t    ) * 72 + nt * 8 + g]);
            b[1] = __float_as_uint(sR2[(kt * 8 + t + 4) * 72 + nt * 8 + g]);
            mma8(acc[0][nt], a[0][kt], b);
            mma8(acc[1][nt], a[1][kt], b);
        }
        #pragma unroll
        for (int mt = 0; mt < 2; mt++)
        #pragma unroll
        for (int nt = 0; nt < 8; nt++) {
            const int r = mt * 16 + g, n = nt * 8 + 2 * t;
            A[(r    ) * ASTR + n    ] = tf32r(fmaxf(acc[mt][nt][0], 0.f));
            A[(r    ) * ASTR + n + 1] = tf32r(fmaxf(acc[mt][nt][1], 0.f));
            A[(r + 8) * ASTR + n    ] = tf32r(fmaxf(acc[mt][nt][2], 0.f));
            A[(r + 8) * ASTR + n + 1] = tf32r(fmaxf(acc[mt][nt][3], 0.f));
        }
    }
    __syncwarp();

    // =============== rgb layer 3: [32x64] @ [64x8] (cols 0..2 real), sigmoid ===============
    {
        unsigned a[2][8][4];
        #pragma unroll
        for (int mt = 0; mt < 2; mt++)
        #pragma unroll
        for (int kt = 0; kt < 8; kt++) {
            const int r = mt * 16 + g, k = kt * 8 + t;
            a[mt][kt][0] = __float_as_uint(A[(r    ) * ASTR + k    ]);
            a[mt][kt][1] = __float_as_uint(A[(r + 8) * ASTR + k    ]);
            a[mt][kt][2] = __float_as_uint(A[(r    ) * ASTR + k + 4]);
            a[mt][kt][3] = __float_as_uint(A[(r + 8) * ASTR + k + 4]);
        }
        float acc[2][4];
        #pragma unroll
        for (int mt = 0; mt < 2; mt++)
        #pragma unroll
        for (int q = 0; q < 4; q++) acc[mt][q] = 0.0f;

        #pragma unroll
        for (int kt = 0; kt < 8; kt++) {
            unsigned b[2];
            b[0] = __float_as_uint(sR3[(kt * 8 + t    ) * 8 + g]);
            b[1] = __float_as_uint(sR3[(kt * 8 + t + 4) * 8 + g]);
            mma8(acc[0], a[0][kt], b);
            mma8(acc[1], a[1][kt], b);
        }
        const int n0 = 2 * t;
        #pragma unroll
        for (int mt = 0; mt < 2; mt++) {
            const int r = mt * 16 + g;
            const int p0 = base + r, p1 = base + r + 8;
            if (n0 < 3) {
                if (p0 < N) out[3 * p0 + n0] = 1.0f / (1.0f + __expf(-acc[mt][0]));
                if (p1 < N) out[3 * p1 + n0] = 1.0f / (1.0f + __expf(-acc[mt][2]));
            }
            if (n0 + 1 < 3) {
                if (p0 < N) out[3 * p0 + n0 + 1] = 1.0f / (1.0f + __expf(-acc[mt][1]));
                if (p1 < N) out[3 * p1 + n0 + 1] = 1.0f / (1.0f + __expf(-acc[mt][3]));
            }
        }
    }
}

extern "C" void kernel_launch(void* const* d_in, const int* in_sizes, int n_in,
                              void* d_out, int out_size)
{
    const float* xyz   = (const float*)d_in[0];
    const float* dirp  = (const float*)d_in[1];
    const float* table = (const float*)d_in[2];
    const float* w1    = (const float*)d_in[3];
    const float* w2    = (const float*)d_in[4];
    const float* wr1   = (const float*)d_in[5];
    const float* wr2   = (const float*)d_in[6];
    const float* wr3   = (const float*)d_in[7];
    float* out = (float*)d_out;

    static int smem_set = 0;
    const int smem_bytes = SMEM_FLOATS * sizeof(float);
    if (!smem_set) {
        cudaFuncSetAttribute(nerf_mma_kernel,
                             cudaFuncAttributeMaxDynamicSharedMemorySize, smem_bytes);
        smem_set = 1;
    }

    const int N = in_sizes[0] / 3;

    // build dense-level pair tables (exact fp32 copies; deterministic)
    build_pair_kernel<<<(PAIR_TOTAL + 255) / 256, 256>>>(table);

    const int grid = (N + 127) / 128;
    nerf_mma_kernel<<<grid, 128, smem_bytes>>>(xyz, dirp, table, w1, w2, wr1, wr2, wr3, out, N);
}

// round 15
// speedup vs baseline: 1.4066x; 1.1376x over previous
#include <cuda_runtime.h>
#include <cuda_bf16.h>
#include <math.h>

#define NLEV 16
#define TBL (1u << 19)

// ---- dense-level pair table: P[i] = (T[i], T[i+1]) as float4, per level ----
// sizes (res+1)^3 for res in {16,22,30,42,58}
#define PAIR_TOTAL 331757
__device__ float4 g_pair[PAIR_TOTAL];
__device__ __constant__ unsigned c_poff[5] = {0u, 4913u, 17080u, 46871u, 126378u};

// ---- dynamic shared layout (float units) ----
// Weight region is PHASED: sigma weights (W1,W2) first, then rgb weights
// (R1,R2,R3) re-staged into the same region behind a __syncthreads().
#define OFF_W1 0            // phase A: [32][72] = 2304
#define OFF_W2 2304         // phase A: [64][24] = 1536 (N=17 padded to 24)
#define OFF_R1 0            // phase B: [32][72] = 2304
#define OFF_R2 2304         // phase B: [64][72] = 4608
#define OFF_R3 6912         // phase B: [64][8]  = 512  (N=3 padded to 8)
#define OFF_ACT 7424        // 4 warps x [32][68] = 8704
#define SMEM_FLOATS 16128   // 64512 bytes -> 3 CTAs/SM
#define ASTR 68

__device__ __constant__ int c_res[16] = {16, 22, 30, 42, 58, 80, 111, 153,
                                         212, 294, 406, 561, 775, 1072, 1481, 2047};

__device__ __forceinline__ float tf32r(float x) {
    unsigned u;
    asm("cvt.rna.tf32.f32 %0, %1;" : "=r"(u) : "f"(x));
    return __uint_as_float(u);
}

__device__ __forceinline__ void mma8(float* c, const unsigned* a, const unsigned* b) {
    asm volatile(
        "mma.sync.aligned.m16n8k8.row.col.f32.tf32.tf32.f32 "
        "{%0,%1,%2,%3}, {%4,%5,%6,%7}, {%8,%9}, {%0,%1,%2,%3};\n"
        : "+f"(c[0]), "+f"(c[1]), "+f"(c[2]), "+f"(c[3])
        : "r"(a[0]), "r"(a[1]), "r"(a[2]), "r"(a[3]), "r"(b[0]), "r"(b[1]));
}

// ================= prep: build dense pair tables (runs each launch, ~10us) =================
__global__ __launch_bounds__(256)
void build_pair_kernel(const float* __restrict__ table)
{
    const int i = blockIdx.x * 256 + threadIdx.x;
    if (i >= PAIR_TOTAL) return;
    int l, off;
    if      (i >= 126378) { l = 4; off = 126378; }
    else if (i >= 46871)  { l = 3; off = 46871; }
    else if (i >= 17080)  { l = 2; off = 17080; }
    else if (i >= 4913)   { l = 1; off = 4913; }
    else                  { l = 0; off = 0; }
    const int j = i - off;
    const float2* T2 = (const float2*)table + (size_t)l * TBL;
    const float2 a = T2[j];
    const float2 b = T2[j + 1];   // stays within the level's TBL slab
    g_pair[i] = make_float4(a.x, a.y, b.x, b.y);
}

__global__ __launch_bounds__(128, 3)
void nerf_mma_kernel(const float* __restrict__ xyz,
                     const float* __restrict__ dirp,
                     const float* __restrict__ table,
                     const float* __restrict__ w1,
                     const float* __restrict__ w2,
                     const float* __restrict__ wr1,
                     const float* __restrict__ wr2,
                     const float* __restrict__ wr3,
                     float* __restrict__ out, int N)
{
    extern __shared__ __align__(16) float sm[];
    float* sW1 = sm + OFF_W1;
    float* sW2 = sm + OFF_W2;

    const int tid = threadIdx.x;

    // -------- phase A staging: sigma weights only --------
    for (int i = tid; i < 32 * 64; i += 128) { int r = i >> 6, c = i & 63; sW1[r * 72 + c] = tf32r(w1[i]); }
    for (int i = tid; i < 64 * 24; i += 128) {
        int r = i / 24, c = i % 24;
        sW2[i] = (c < 17) ? tf32r(w2[r * 17 + c]) : 0.0f;
    }
    __syncthreads();

    const int ln = tid & 31;
    const int wp = tid >> 5;
    const int g  = ln >> 2;      // group id (0..7)
    const int t  = ln & 3;       // thread-in-group (0..3)
    float* A = sm + OFF_ACT + wp * (32 * ASTR);

    const int base = blockIdx.x * 128 + wp * 32;   // first point of this warp's tile
    const int idx  = base + ln;
    const int pidx = idx < N ? idx : N - 1;

    // -------- direction load + SH basis (compute early, keep in regs) --------
    float sh[16];
    {
        const float dx = dirp[3 * pidx + 0] * 2.0f - 1.0f;
        const float dy = dirp[3 * pidx + 1] * 2.0f - 1.0f;
        const float dz = dirp[3 * pidx + 2] * 2.0f - 1.0f;
        const float x2 = dx * dx, y2 = dy * dy, z2 = dz * dz;
        const float xy = dx * dy, yz = dy * dz, xz = dx * dz;
        sh[0]  = 0.28209479177387814f;
        sh[1]  = -0.48860251190291987f * dy;
        sh[2]  = 0.48860251190291987f * dz;
        sh[3]  = -0.48860251190291987f * dx;
        sh[4]  = 1.0925484305920792f * xy;
        sh[5]  = -1.0925484305920792f * yz;
        sh[6]  = 0.94617469575756f * z2 - 0.31539156525252f;
        sh[7]  = -1.0925484305920792f * xz;
        sh[8]  = 0.5462742152960396f * (x2 - y2);
        sh[9]  = 0.5900435899266435f * dy * (-3.0f * x2 + y2);
        sh[10] = 2.890611442640554f * xy * dz;
        sh[11] = 0.4570457994644657f * dy * (1.0f - 5.0f * z2);
        sh[12] = 0.3731763325901154f * dz * (5.0f * z2 - 3.0f);
        sh[13] = 0.4570457994644657f * dx * (1.0f - 5.0f * z2);
        sh[14] = 1.445305721320277f * dz * (x2 - y2);
        sh[15] = 0.5900435899266435f * dx * (-x2 + 3.0f * y2);
    }

    // -------- hash-grid encode -> act row ln, cols 0..31 (tf32-rounded) --------
    {
        const float x = xyz[3 * pidx + 0];
        const float y = xyz[3 * pidx + 1];
        const float z = xyz[3 * pidx + 2];
        float* arow = A + ln * ASTR;

        // dense levels 0..4: x-corner pairs merged via pair table (4x LDG.128)
        #pragma unroll
        for (int l = 0; l < 5; l++) {
            const int res = c_res[l];
            const float rf = (float)res;
            const float px = x * rf, py = y * rf, pz = z * rf;
            const float fx = floorf(px), fy = floorf(py), fz = floorf(pz);
            const float wx = px - fx, wy = py - fy, wz = pz - fz;
            const unsigned X = (unsigned)fx, Y = (unsigned)fy, Z = (unsigned)fz;

            const unsigned s  = (unsigned)(res + 1);
            const unsigned s2 = s * s;
            const unsigned b0 = X + Y * s + Z * s2;

            const float4* P = g_pair + c_poff[l];
            const float4 q0 = __ldg(P + b0);            // corners (c0, c1)
            const float4 q1 = __ldg(P + b0 + s);        // corners (c2, c3)
            const float4 q2 = __ldg(P + b0 + s2);       // corners (c4, c5)
            const float4 q3 = __ldg(P + b0 + s2 + s);   // corners (c6, c7)

            const float wx0 = 1.0f - wx, wy0 = 1.0f - wy, wz0 = 1.0f - wz;
            const float w00 = wy0 * wz0, w10 = wy * wz0, w01 = wy0 * wz, w11 = wy * wz;
            const float c0 = wx0 * w00, c1 = wx * w00;
            const float c2 = wx0 * w10, c3 = wx * w10;
            const float c4 = wx0 * w01, c5 = wx * w01;
            const float c6 = wx0 * w11, c7 = wx * w11;

            float e0 = q0.x * c0; float e1 = q0.y * c0;
            e0 = fmaf(q0.z, c1, e0); e1 = fmaf(q0.w, c1, e1);
            e0 = fmaf(q1.x, c2, e0); e1 = fmaf(q1.y, c2, e1);
            e0 = fmaf(q1.z, c3, e0); e1 = fmaf(q1.w, c3, e1);
            e0 = fmaf(q2.x, c4, e0); e1 = fmaf(q2.y, c4, e1);
            e0 = fmaf(q2.z, c5, e0); e1 = fmaf(q2.w, c5, e1);
            e0 = fmaf(q3.x, c6, e0); e1 = fmaf(q3.y, c6, e1);
            e0 = fmaf(q3.z, c7, e0); e1 = fmaf(q3.w, c7, e1);

            arow[2 * l + 0] = tf32r(e0);
            arow[2 * l + 1] = tf32r(e1);
        }

        // hashed levels 5..15
        #pragma unroll
        for (int l = 5; l < NLEV; l++) {
            const int res = c_res[l];
            const float rf = (float)res;
            const float px = x * rf, py = y * rf, pz = z * rf;
            const float fx = floorf(px), fy = floorf(py), fz = floorf(pz);
            const float wx = px - fx, wy = py - fy, wz = pz - fz;
            const unsigned X = (unsigned)fx, Y = (unsigned)fy, Z = (unsigned)fz;

            const unsigned P1 = 2654435761u, P2 = 805459861u;
            const unsigned hx0 = X, hx1 = X + 1u;
            const unsigned hy0 = Y * P1, hy1 = (Y + 1u) * P1;
            const unsigned hz0 = Z * P2, hz1 = (Z + 1u) * P2;
            const unsigned M = TBL - 1u;
            const unsigned id0 = (hx0 ^ hy0 ^ hz0) & M;  const unsigned id1 = (hx1 ^ hy0 ^ hz0) & M;
            const unsigned id2 = (hx0 ^ hy1 ^ hz0) & M;  const unsigned id3 = (hx1 ^ hy1 ^ hz0) & M;
            const unsigned id4 = (hx0 ^ hy0 ^ hz1) & M;  const unsigned id5 = (hx1 ^ hy0 ^ hz1) & M;
            const unsigned id6 = (hx0 ^ hy1 ^ hz1) & M;  const unsigned id7 = (hx1 ^ hy1 ^ hz1) & M;

            const float2* tl = (const float2*)table + (size_t)l * TBL;
            const float2 f0 = __ldg(tl + id0);
            const float2 f1 = __ldg(tl + id1);
            const float2 f2 = __ldg(tl + id2);
            const float2 f3 = __ldg(tl + id3);
            const float2 f4 = __ldg(tl + id4);
            const float2 f5 = __ldg(tl + id5);
            const float2 f6 = __ldg(tl + id6);
            const float2 f7 = __ldg(tl + id7);

            const float wx0 = 1.0f - wx, wy0 = 1.0f - wy, wz0 = 1.0f - wz;
            const float w00 = wy0 * wz0, w10 = wy * wz0, w01 = wy0 * wz, w11 = wy * wz;
            const float c0 = wx0 * w00, c1 = wx * w00;
            const float c2 = wx0 * w10, c3 = wx * w10;
            const float c4 = wx0 * w01, c5 = wx * w01;
            const float c6 = wx0 * w11, c7 = wx * w11;

            float e0 = f0.x * c0; float e1 = f0.y * c0;
            e0 = fmaf(f1.x, c1, e0); e1 = fmaf(f1.y, c1, e1);
            e0 = fmaf(f2.x, c2, e0); e1 = fmaf(f2.y, c2, e1);
            e0 = fmaf(f3.x, c3, e0); e1 = fmaf(f3.y, c3, e1);
            e0 = fmaf(f4.x, c4, e0); e1 = fmaf(f4.y, c4, e1);
            e0 = fmaf(f5.x, c5, e0); e1 = fmaf(f5.y, c5, e1);
            e0 = fmaf(f6.x, c6, e0); e1 = fmaf(f6.y, c6, e1);
            e0 = fmaf(f7.x, c7, e0); e1 = fmaf(f7.y, c7, e1);

            arow[2 * l + 0] = tf32r(e0);
            arow[2 * l + 1] = tf32r(e1);
        }
    }
    __syncwarp();

    // =============== sigma layer 1: [32x32] @ [32x64], relu ===============
    {
        unsigned a[2][4][4];
        #pragma unroll
        for (int mt = 0; mt < 2; mt++)
        #pragma unroll
        for (int kt = 0; kt < 4; kt++) {
            const int r = mt * 16 + g, k = kt * 8 + t;
            a[mt][kt][0] = __float_as_uint(A[(r    ) * ASTR + k    ]);
            a[mt][kt][1] = __float_as_uint(A[(r + 8) * ASTR + k    ]);
            a[mt][kt][2] = __float_as_uint(A[(r    ) * ASTR + k + 4]);
            a[mt][kt][3] = __float_as_uint(A[(r + 8) * ASTR + k + 4]);
        }
        __syncwarp();
        float acc[2][8][4];
        #pragma unroll
        for (int mt = 0; mt < 2; mt++)
        #pragma unroll
        for (int nt = 0; nt < 8; nt++)
        #pragma unroll
        for (int q = 0; q < 4; q++) acc[mt][nt][q] = 0.0f;

        #pragma unroll
        for (int nt = 0; nt < 8; nt++)
        #pragma unroll
        for (int kt = 0; kt < 4; kt++) {
            unsigned b[2];
            b[0] = __float_as_uint(sW1[(kt * 8 + t    ) * 72 + nt * 8 + g]);
            b[1] = __float_as_uint(sW1[(kt * 8 + t + 4) * 72 + nt * 8 + g]);
            mma8(acc[0][nt], a[0][kt], b);
            mma8(acc[1][nt], a[1][kt], b);
        }
        #pragma unroll
        for (int mt = 0; mt < 2; mt++)
        #pragma unroll
        for (int nt = 0; nt < 8; nt++) {
            const int r = mt * 16 + g, n = nt * 8 + 2 * t;
            A[(r    ) * ASTR + n    ] = tf32r(fmaxf(acc[mt][nt][0], 0.f));
            A[(r    ) * ASTR + n + 1] = tf32r(fmaxf(acc[mt][nt][1], 0.f));
            A[(r + 8) * ASTR + n    ] = tf32r(fmaxf(acc[mt][nt][2], 0.f));
            A[(r + 8) * ASTR + n + 1] = tf32r(fmaxf(acc[mt][nt][3], 0.f));
        }
    }
    __syncwarp();

    // =============== sigma layer 2: [32x64] @ [64x24], no activation ===============
    {
        unsigned a[2][8][4];
        #pragma unroll
        for (int mt = 0; mt < 2; mt++)
        #pragma unroll
        for (int kt = 0; kt < 8; kt++) {
            const int r = mt * 16 + g, k = kt * 8 + t;
            a[mt][kt][0] = __float_as_uint(A[(r    ) * ASTR + k    ]);
            a[mt][kt][1] = __float_as_uint(A[(r + 8) * ASTR + k    ]);
            a[mt][kt][2] = __float_as_uint(A[(r    ) * ASTR + k + 4]);
            a[mt][kt][3] = __float_as_uint(A[(r + 8) * ASTR + k + 4]);
        }
        __syncwarp();   // everyone finished reading h before we overwrite act

        float acc[2][3][4];
        #pragma unroll
        for (int mt = 0; mt < 2; mt++)
        #pragma unroll
        for (int nt = 0; nt < 3; nt++)
        #pragma unroll
        for (int q = 0; q < 4; q++) acc[mt][nt][q] = 0.0f;

        #pragma unroll
        for (int nt = 0; nt < 3; nt++)
        #pragma unroll
        for (int kt = 0; kt < 8; kt++) {
            unsigned b[2];
            b[0] = __float_as_uint(sW2[(kt * 8 + t    ) * 24 + nt * 8 + g]);
            b[1] = __float_as_uint(sW2[(kt * 8 + t + 4) * 24 + nt * 8 + g]);
            mma8(acc[0][nt], a[0][kt], b);
            mma8(acc[1][nt], a[1][kt], b);
        }

        // SH basis -> act cols 0..15 (own row)
        #pragma unroll
        for (int i = 0; i < 16; i++) A[ln * ASTR + i] = tf32r(sh[i]);

        // sigma (col 0) -> global; geometry cols 1..16 -> act cols 16..31
        #pragma unroll
        for (int mt = 0; mt < 2; mt++) {
            const int r = mt * 16 + g;
            #pragma unroll
            for (int nt = 0; nt < 3; nt++) {
                const int n0 = nt * 8 + 2 * t;
                const float v0 = acc[mt][nt][0], v1 = acc[mt][nt][1];
                const float v2 = acc[mt][nt][2], v3 = acc[mt][nt][3];
                if (n0 == 0) {
                    const int p0 = base + r, p1 = base + r + 8;
                    if (p0 < N) out[(size_t)3 * N + p0] = fmaxf(v0, 0.f);
                    if (p1 < N) out[(size_t)3 * N + p1] = fmaxf(v2, 0.f);
                } else if (n0 >= 1 && n0 <= 16) {
                    A[(r    ) * ASTR + 15 + n0] = tf32r(v0);
                    A[(r + 8) * ASTR + 15 + n0] = tf32r(v2);
                }
                const int n1 = n0 + 1;
                if (n1 >= 1 && n1 <= 16) {
                    A[(r    ) * ASTR + 15 + n1] = tf32r(v1);
                    A[(r + 8) * ASTR + 15 + n1] = tf32r(v3);
                }
            }
        }
    }

    // -------- phase B staging: rgb weights overwrite sigma weights --------
    __syncthreads();   // all warps done reading sW1/sW2
    {
        float* sR1w = sm + OFF_R1;
        float* sR2w = sm + OFF_R2;
        float* sR3w = sm + OFF_R3;
        for (int i = tid; i < 32 * 64; i += 128) { int r = i >> 6, c = i & 63; sR1w[r * 72 + c] = tf32r(wr1[i]); }
        for (int i = tid; i < 64 * 64; i += 128) { int r = i >> 6, c = i & 63; sR2w[r * 72 + c] = tf32r(wr2[i]); }
        for (int i = tid; i < 64 * 8;  i += 128) {
            int r = i >> 3, c = i & 7;
            sR3w[i] = (c < 3) ? tf32r(wr3[r * 3 + c]) : 0.0f;
        }
    }
    __syncthreads();
    const float* sR1 = sm + OFF_R1;
    const float* sR2 = sm + OFF_R2;
    const float* sR3 = sm + OFF_R3;

    // =============== rgb layer 1: [32x32] @ [32x64], relu ===============
    {
        unsigned a[2][4][4];
        #pragma unroll
        for (int mt = 0; mt < 2; mt++)
        #pragma unroll
        for (int kt = 0; kt < 4; kt++) {
            const int r = mt * 16 + g, k = kt * 8 + t;
            a[mt][kt][0] = __float_as_uint(A[(r    ) * ASTR + k    ]);
            a[mt][kt][1] = __float_as_uint(A[(r + 8) * ASTR + k    ]);
            a[mt][kt][2] = __float_as_uint(A[(r    ) * ASTR + k + 4]);
            a[mt][kt][3] = __float_as_uint(A[(r + 8) * ASTR + k + 4]);
        }
        __syncwarp();
        float acc[2][8][4];
        #pragma unroll
        for (int mt = 0; mt < 2; mt++)
        #pragma unroll
        for (int nt = 0; nt < 8; nt++)
        #pragma unroll
        for (int q = 0; q < 4; q++) acc[mt][nt][q] = 0.0f;

        #pragma unroll
        for (int nt = 0; nt < 8; nt++)
        #pragma unroll
        for (int kt = 0; kt < 4; kt++) {
            unsigned b[2];
            b[0] = __float_as_uint(sR1[(kt * 8 + t    ) * 72 + nt * 8 + g]);
            b[1] = __float_as_uint(sR1[(kt * 8 + t + 4) * 72 + nt * 8 + g]);
            mma8(acc[0][nt], a[0][kt], b);
            mma8(acc[1][nt], a[1][kt], b);
        }
        #pragma unroll
        for (int mt = 0; mt < 2; mt++)
        #pragma unroll
        for (int nt = 0; nt < 8; nt++) {
            const int r = mt * 16 + g, n = nt * 8 + 2 * t;
            A[(r    ) * ASTR + n    ] = tf32r(fmaxf(acc[mt][nt][0], 0.f));
            A[(r    ) * ASTR + n + 1] = tf32r(fmaxf(acc[mt][nt][1], 0.f));
            A[(r + 8) * ASTR + n    ] = tf32r(fmaxf(acc[mt][nt][2], 0.f));
            A[(r + 8) * ASTR + n + 1] = tf32r(fmaxf(acc[mt][nt][3], 0.f));
        }
    }
    __syncwarp();

    // =============== rgb layer 2: [32x64] @ [64x64], relu ===============
    {
        unsigned a[2][8][4];
        #pragma unroll
        for (int mt = 0; mt < 2; mt++)
        #pragma unroll
        for (int kt = 0; kt < 8; kt++) {
            const int r = mt * 16 + g, k = kt * 8 + t;
            a[mt][kt][0] = __float_as_uint(A[(r    ) * ASTR + k    ]);
            a[mt][kt][1] = __float_as_uint(A[(r + 8) * ASTR + k    ]);
            a[mt][kt][2] = __float_as_uint(A[(r    ) * ASTR + k + 4]);
            a[mt][kt][3] = __float_as_uint(A[(r + 8) * ASTR + k + 4]);
        }
        __syncwarp();
        float acc[2][8][4];
        #pragma unroll
        for (int mt = 0; mt < 2; mt++)
        #pragma unroll
        for (int nt = 0; nt < 8; nt++)
        #pragma unroll
        for (int q = 0; q < 4; q++) acc[mt][nt][q] = 0.0f;

        #pragma unroll
        for (int nt = 0; nt < 8; nt++)
        #pragma unroll
        for (int kt = 0; kt < 8; kt++) {
            unsigned b[2];
            b[0] = __float_as_uint(sR2[(kt * 8 + t    ) * 72 + nt * 8 + g]);
            b[1] = __float_as_uint(sR2[(kt * 8 + t + 4) * 72 + nt * 8 + g]);
            mma8(acc[0][nt], a[0][kt], b);
            mma8(acc[1][nt], a[1][kt], b);
        }
        #pragma unroll
        for (int mt = 0; mt < 2; mt++)
        #pragma unroll
        for (int nt = 0; nt < 8; nt++) {
            const int r = mt * 16 + g, n = nt * 8 + 2 * t;
            A[(r    ) * ASTR + n    ] = tf32r(fmaxf(acc[mt][nt][0], 0.f));
            A[(r    ) * ASTR + n + 1] = tf32r(fmaxf(acc[mt][nt][1], 0.f));
            A[(r + 8) * ASTR + n    ] = tf32r(fmaxf(acc[mt][nt][2], 0.f));
            A[(r + 8) * ASTR + n + 1] = tf32r(fmaxf(acc[mt][nt][3], 0.f));
        }
    }
    __syncwarp();

    // =============== rgb layer 3: [32x64] @ [64x8] (cols 0..2 real), sigmoid ===============
    {
        unsigned a[2][8][4];
        #pragma unroll
        for (int mt = 0; mt < 2; mt++)
        #pragma unroll
        for (int kt = 0; kt < 8; kt++) {
            const int r = mt * 16 + g, k = kt * 8 + t;
            a[mt][kt][0] = __float_as_uint(A[(r    ) * ASTR + k    ]);
            a[mt][kt][1] = __float_as_uint(A[(r + 8) * ASTR + k    ]);
            a[mt][kt][2] = __float_as_uint(A[(r    ) * ASTR + k + 4]);
            a[mt][kt][3] = __float_as_uint(A[(r + 8) * ASTR + k + 4]);
        }
        float acc[2][4];
        #pragma unroll
        for (int mt = 0; mt < 2; mt++)
        #pragma unroll
        for (int q = 0; q < 4; q++) acc[mt][q] = 0.0f;

        #pragma unroll
        for (int kt = 0; kt < 8; kt++) {
            unsigned b[2];
            b[0] = __float_as_uint(sR3[(kt * 8 + t    ) * 8 + g]);
            b[1] = __float_as_uint(sR3[(kt * 8 + t + 4) * 8 + g]);
            mma8(acc[0], a[0][kt], b);
            mma8(acc[1], a[1][kt], b);
        }
        const int n0 = 2 * t;
        #pragma unroll
        for (int mt = 0; mt < 2; mt++) {
            const int r = mt * 16 + g;
            const int p0 = base + r, p1 = base + r + 8;
            if (n0 < 3) {
                if (p0 < N) out[3 * p0 + n0] = 1.0f / (1.0f + __expf(-acc[mt][0]));
                if (p1 < N) out[3 * p1 + n0] = 1.0f / (1.0f + __expf(-acc[mt][2]));
            }
            if (n0 + 1 < 3) {
                if (p0 < N) out[3 * p0 + n0 + 1] = 1.0f / (1.0f + __expf(-acc[mt][1]));
                if (p1 < N) out[3 * p1 + n0 + 1] = 1.0f / (1.0f + __expf(-acc[mt][3]));
            }
        }
    }
}

extern "C" void kernel_launch(void* const* d_in, const int* in_sizes, int n_in,
                              void* d_out, int out_size)
{
    const float* xyz   = (const float*)d_in[0];
    const float* dirp  = (const float*)d_in[1];
    const float* table = (const float*)d_in[2];
    const float* w1    = (const float*)d_in[3];
    const float* w2    = (const float*)d_in[4];
    const float* wr1   = (const float*)d_in[5];
    const float* wr2   = (const float*)d_in[6];
    const float* wr3   = (const float*)d_in[7];
    float* out = (float*)d_out;

    static int smem_set = 0;
    const int smem_bytes = SMEM_FLOATS * sizeof(float);
    if (!smem_set) {
        cudaFuncSetAttribute(nerf_mma_kernel,
                             cudaFuncAttributeMaxDynamicSharedMemorySize, smem_bytes);
        smem_set = 1;
    }

    const int N = in_sizes[0] / 3;

    // build dense-level pair tables (exact fp32 copies; deterministic)
    build_pair_kernel<<<(PAIR_TOTAL + 255) / 256, 256>>>(table);

    const int grid = (N + 127) / 128;
    nerf_mma_kernel<<<grid, 128, smem_bytes>>>(xyz, dirp, table, w1, w2, wr1, wr2, wr3, out, N);
}

// round 17
// speedup vs baseline: 1.4776x; 1.0505x over previous
#include <cuda_runtime.h>
#include <cuda_bf16.h>
#include <math.h>

#define NLEV 16
#define TBL (1u << 19)
#define NMAX (1 << 21)

// scratch: enc features, feature-major [32][N] (coalesced for both kernels)
__device__ float g_enc[32u * (unsigned)NMAX];

// ---- dense-level pair table: P[i] = (T[i], T[i+1]) as float4, per level ----
#define PAIR_TOTAL 331757
__device__ float4 g_pair[PAIR_TOTAL];
__device__ __constant__ unsigned c_poff[5] = {0u, 4913u, 17080u, 46871u, 126378u};

// ---- K2 dynamic shared layout (float units), 3-phase weight staging ----
//   phase A: W1 [32][72]=2304 @0, W2 [64][24]=1536 @2304   (3840)
//   phase B: R1 [32][72]=2304 @0
//   phase C: R2 [64][72]=4608 @0, R3 [64][8]=512 @4608     (5120)
#define OFF_W1 0
#define OFF_W2 2304
#define OFF_R1 0
#define OFF_R2 0
#define OFF_R3 4608
#define OFF_ACT 5120        // 4 warps x [32][68] = 8704
#define SMEM_FLOATS 13824   // 55296 bytes -> 4 CTAs/SM (if regs allow)
#define ASTR 68

__device__ __constant__ int c_res[16] = {16, 22, 30, 42, 58, 80, 111, 153,
                                         212, 294, 406, 561, 775, 1072, 1481, 2047};

__device__ __forceinline__ float tf32r(float x) {
    unsigned u;
    asm("cvt.rna.tf32.f32 %0, %1;" : "=r"(u) : "f"(x));
    return __uint_as_float(u);
}

__device__ __forceinline__ void mma8(float* c, const unsigned* a, const unsigned* b) {
    asm volatile(
        "mma.sync.aligned.m16n8k8.row.col.f32.tf32.tf32.f32 "
        "{%0,%1,%2,%3}, {%4,%5,%6,%7}, {%8,%9}, {%0,%1,%2,%3};\n"
        : "+f"(c[0]), "+f"(c[1]), "+f"(c[2]), "+f"(c[3])
        : "r"(a[0]), "r"(a[1]), "r"(a[2]), "r"(a[3]), "r"(b[0]), "r"(b[1]));
}

// ================= K0: build dense pair tables =================
__global__ __launch_bounds__(256)
void build_pair_kernel(const float* __restrict__ table)
{
    const int i = blockIdx.x * 256 + threadIdx.x;
    if (i >= PAIR_TOTAL) return;
    int l, off;
    if      (i >= 126378) { l = 4; off = 126378; }
    else if (i >= 46871)  { l = 3; off = 46871; }
    else if (i >= 17080)  { l = 2; off = 17080; }
    else if (i >= 4913)   { l = 1; off = 4913; }
    else                  { l = 0; off = 0; }
    const int j = i - off;
    const float2* T2 = (const float2*)table + (size_t)l * TBL;
    const float2 a = T2[j];
    const float2 b = T2[j + 1];
    g_pair[i] = make_float4(a.x, a.y, b.x, b.y);
}

// ================= K1: hash-grid encode (gather-saturating, high occupancy) =================
__global__ __launch_bounds__(256)
void encode_kernel(const float* __restrict__ xyz,
                   const float* __restrict__ table, int N)
{
    const int idx = blockIdx.x * 256 + threadIdx.x;
    if (idx >= N) return;

    const float x = xyz[3 * idx + 0];
    const float y = xyz[3 * idx + 1];
    const float z = xyz[3 * idx + 2];

    // dense levels 0..4 via pair table (4x LDG.128 each)
    #pragma unroll
    for (int l = 0; l < 5; l++) {
        const int res = c_res[l];
        const float rf = (float)res;
        const float px = x * rf, py = y * rf, pz = z * rf;
        const float fx = floorf(px), fy = floorf(py), fz = floorf(pz);
        const float wx = px - fx, wy = py - fy, wz = pz - fz;
        const unsigned X = (unsigned)fx, Y = (unsigned)fy, Z = (unsigned)fz;

        const unsigned s  = (unsigned)(res + 1);
        const unsigned s2 = s * s;
        const unsigned b0 = X + Y * s + Z * s2;

        const float4* P = g_pair + c_poff[l];
        const float4 q0 = __ldg(P + b0);
        const float4 q1 = __ldg(P + b0 + s);
        const float4 q2 = __ldg(P + b0 + s2);
        const float4 q3 = __ldg(P + b0 + s2 + s);

        const float wx0 = 1.0f - wx, wy0 = 1.0f - wy, wz0 = 1.0f - wz;
        const float w00 = wy0 * wz0, w10 = wy * wz0, w01 = wy0 * wz, w11 = wy * wz;
        const float c0 = wx0 * w00, c1 = wx * w00;
        const float c2 = wx0 * w10, c3 = wx * w10;
        const float c4 = wx0 * w01, c5 = wx * w01;
        const float c6 = wx0 * w11, c7 = wx * w11;

        float e0 = q0.x * c0; float e1 = q0.y * c0;
        e0 = fmaf(q0.z, c1, e0); e1 = fmaf(q0.w, c1, e1);
        e0 = fmaf(q1.x, c2, e0); e1 = fmaf(q1.y, c2, e1);
        e0 = fmaf(q1.z, c3, e0); e1 = fmaf(q1.w, c3, e1);
        e0 = fmaf(q2.x, c4, e0); e1 = fmaf(q2.y, c4, e1);
        e0 = fmaf(q2.z, c5, e0); e1 = fmaf(q2.w, c5, e1);
        e0 = fmaf(q3.x, c6, e0); e1 = fmaf(q3.y, c6, e1);
        e0 = fmaf(q3.z, c7, e0); e1 = fmaf(q3.w, c7, e1);

        g_enc[(size_t)(2 * l + 0) * N + idx] = tf32r(e0);
        g_enc[(size_t)(2 * l + 1) * N + idx] = tf32r(e1);
    }

    // hashed levels 5..15
    #pragma unroll
    for (int l = 5; l < NLEV; l++) {
        const int res = c_res[l];
        const float rf = (float)res;
        const float px = x * rf, py = y * rf, pz = z * rf;
        const float fx = floorf(px), fy = floorf(py), fz = floorf(pz);
        const float wx = px - fx, wy = py - fy, wz = pz - fz;
        const unsigned X = (unsigned)fx, Y = (unsigned)fy, Z = (unsigned)fz;

        const unsigned P1 = 2654435761u, P2 = 805459861u;
        const unsigned hx0 = X, hx1 = X + 1u;
        const unsigned hy0 = Y * P1, hy1 = (Y + 1u) * P1;
        const unsigned hz0 = Z * P2, hz1 = (Z + 1u) * P2;
        const unsigned M = TBL - 1u;
        const unsigned id0 = (hx0 ^ hy0 ^ hz0) & M;  const unsigned id1 = (hx1 ^ hy0 ^ hz0) & M;
        const unsigned id2 = (hx0 ^ hy1 ^ hz0) & M;  const unsigned id3 = (hx1 ^ hy1 ^ hz0) & M;
        const unsigned id4 = (hx0 ^ hy0 ^ hz1) & M;  const unsigned id5 = (hx1 ^ hy0 ^ hz1) & M;
        const unsigned id6 = (hx0 ^ hy1 ^ hz1) & M;  const unsigned id7 = (hx1 ^ hy1 ^ hz1) & M;

        const float2* tl = (const float2*)table + (size_t)l * TBL;
        const float2 f0 = __ldg(tl + id0);
        const float2 f1 = __ldg(tl + id1);
        const float2 f2 = __ldg(tl + id2);
        const float2 f3 = __ldg(tl + id3);
        const float2 f4 = __ldg(tl + id4);
        const float2 f5 = __ldg(tl + id5);
        const float2 f6 = __ldg(tl + id6);
        const float2 f7 = __ldg(tl + id7);

        const float wx0 = 1.0f - wx, wy0 = 1.0f - wy, wz0 = 1.0f - wz;
        const float w00 = wy0 * wz0, w10 = wy * wz0, w01 = wy0 * wz, w11 = wy * wz;
        const float c0 = wx0 * w00, c1 = wx * w00;
        const float c2 = wx0 * w10, c3 = wx * w10;
        const float c4 = wx0 * w01, c5 = wx * w01;
        const float c6 = wx0 * w11, c7 = wx * w11;

        float e0 = f0.x * c0; float e1 = f0.y * c0;
        e0 = fmaf(f1.x, c1, e0); e1 = fmaf(f1.y, c1, e1);
        e0 = fmaf(f2.x, c2, e0); e1 = fmaf(f2.y, c2, e1);
        e0 = fmaf(f3.x, c3, e0); e1 = fmaf(f3.y, c3, e1);
        e0 = fmaf(f4.x, c4, e0); e1 = fmaf(f4.y, c4, e1);
        e0 = fmaf(f5.x, c5, e0); e1 = fmaf(f5.y, c5, e1);
        e0 = fmaf(f6.x, c6, e0); e1 = fmaf(f6.y, c6, e1);
        e0 = fmaf(f7.x, c7, e0); e1 = fmaf(f7.y, c7, e1);

        g_enc[(size_t)(2 * l + 0) * N + idx] = tf32r(e0);
        g_enc[(size_t)(2 * l + 1) * N + idx] = tf32r(e1);
    }
}

// ================= K2: MMA MLP kernel (tensor/LDS-bound, no gathers) =================
__global__ __launch_bounds__(128)
void nerf_mma_kernel(const float* __restrict__ dirp,
                     const float* __restrict__ w1,
                     const float* __restrict__ w2,
                     const float* __restrict__ wr1,
                     const float* __restrict__ wr2,
                     const float* __restrict__ wr3,
                     float* __restrict__ out, int N)
{
    extern __shared__ __align__(16) float sm[];
    const int tid = threadIdx.x;

    // -------- phase A staging: sigma weights --------
    {
        float* sW1 = sm + OFF_W1;
        float* sW2 = sm + OFF_W2;
        for (int i = tid; i < 32 * 64; i += 128) { int r = i >> 6, c = i & 63; sW1[r * 72 + c] = tf32r(w1[i]); }
        for (int i = tid; i < 64 * 24; i += 128) {
            int r = i / 24, c = i % 24;
            sW2[i] = (c < 17) ? tf32r(w2[r * 17 + c]) : 0.0f;
        }
    }
    __syncthreads();

    const int ln = tid & 31;
    const int wp = tid >> 5;
    const int g  = ln >> 2;      // group id (0..7)
    const int t  = ln & 3;       // thread-in-group (0..3)
    float* A = sm + OFF_ACT + wp * (32 * ASTR);

    const int base = blockIdx.x * 128 + wp * 32;
    const int idx  = base + ln;
    const int pidx = idx < N ? idx : N - 1;

    // -------- SH basis (registers) --------
    float sh[16];
    {
        const float dx = dirp[3 * pidx + 0] * 2.0f - 1.0f;
        const float dy = dirp[3 * pidx + 1] * 2.0f - 1.0f;
        const float dz = dirp[3 * pidx + 2] * 2.0f - 1.0f;
        const float x2 = dx * dx, y2 = dy * dy, z2 = dz * dz;
        const float xy = dx * dy, yz = dy * dz, xz = dx * dz;
        sh[0]  = 0.28209479177387814f;
        sh[1]  = -0.48860251190291987f * dy;
        sh[2]  = 0.48860251190291987f * dz;
        sh[3]  = -0.48860251190291987f * dx;
        sh[4]  = 1.0925484305920792f * xy;
        sh[5]  = -1.0925484305920792f * yz;
        sh[6]  = 0.94617469575756f * z2 - 0.31539156525252f;
        sh[7]  = -1.0925484305920792f * xz;
        sh[8]  = 0.5462742152960396f * (x2 - y2);
        sh[9]  = 0.5900435899266435f * dy * (-3.0f * x2 + y2);
        sh[10] = 2.890611442640554f * xy * dz;
        sh[11] = 0.4570457994644657f * dy * (1.0f - 5.0f * z2);
        sh[12] = 0.3731763325901154f * dz * (5.0f * z2 - 3.0f);
        sh[13] = 0.4570457994644657f * dx * (1.0f - 5.0f * z2);
        sh[14] = 1.445305721320277f * dz * (x2 - y2);
        sh[15] = 0.5900435899266435f * dx * (-x2 + 3.0f * y2);
    }

    // -------- load enc from scratch (feature-major; fully coalesced) --------
    {
        float* arow = A + ln * ASTR;
        #pragma unroll
        for (int f = 0; f < 32; f++)
            arow[f] = __ldg(&g_enc[(size_t)f * N + pidx]);
    }
    __syncwarp();

    // =============== sigma layer 1: [32x32] @ [32x64], relu ===============
    {
        const float* sW1 = sm + OFF_W1;
        unsigned a[2][4][4];
        #pragma unroll
        for (int mt = 0; mt < 2; mt++)
        #pragma unroll
        for (int kt = 0; kt < 4; kt++) {
            const int r = mt * 16 + g, k = kt * 8 + t;
            a[mt][kt][0] = __float_as_uint(A[(r    ) * ASTR + k    ]);
            a[mt][kt][1] = __float_as_uint(A[(r + 8) * ASTR + k    ]);
            a[mt][kt][2] = __float_as_uint(A[(r    ) * ASTR + k + 4]);
            a[mt][kt][3] = __float_as_uint(A[(r + 8) * ASTR + k + 4]);
        }
        __syncwarp();
        float acc[2][8][4];
        #pragma unroll
        for (int mt = 0; mt < 2; mt++)
        #pragma unroll
        for (int nt = 0; nt < 8; nt++)
        #pragma unroll
        for (int q = 0; q < 4; q++) acc[mt][nt][q] = 0.0f;

        #pragma unroll
        for (int nt = 0; nt < 8; nt++)
        #pragma unroll
        for (int kt = 0; kt < 4; kt++) {
            unsigned b[2];
            b[0] = __float_as_uint(sW1[(kt * 8 + t    ) * 72 + nt * 8 + g]);
            b[1] = __float_as_uint(sW1[(kt * 8 + t + 4) * 72 + nt * 8 + g]);
            mma8(acc[0][nt], a[0][kt], b);
            mma8(acc[1][nt], a[1][kt], b);
        }
        #pragma unroll
        for (int mt = 0; mt < 2; mt++)
        #pragma unroll
        for (int nt = 0; nt < 8; nt++) {
            const int r = mt * 16 + g, n = nt * 8 + 2 * t;
            A[(r    ) * ASTR + n    ] = tf32r(fmaxf(acc[mt][nt][0], 0.f));
            A[(r    ) * ASTR + n + 1] = tf32r(fmaxf(acc[mt][nt][1], 0.f));
            A[(r + 8) * ASTR + n    ] = tf32r(fmaxf(acc[mt][nt][2], 0.f));
            A[(r + 8) * ASTR + n + 1] = tf32r(fmaxf(acc[mt][nt][3], 0.f));
        }
    }
    __syncwarp();

    // =============== sigma layer 2: [32x64] @ [64x24] ===============
    {
        const float* sW2 = sm + OFF_W2;
        unsigned a[2][8][4];
        #pragma unroll
        for (int mt = 0; mt < 2; mt++)
        #pragma unroll
        for (int kt = 0; kt < 8; kt++) {
            const int r = mt * 16 + g, k = kt * 8 + t;
            a[mt][kt][0] = __float_as_uint(A[(r    ) * ASTR + k    ]);
            a[mt][kt][1] = __float_as_uint(A[(r + 8) * ASTR + k    ]);
            a[mt][kt][2] = __float_as_uint(A[(r    ) * ASTR + k + 4]);
            a[mt][kt][3] = __float_as_uint(A[(r + 8) * ASTR + k + 4]);
        }
        __syncwarp();

        float acc[2][3][4];
        #pragma unroll
        for (int mt = 0; mt < 2; mt++)
        #pragma unroll
        for (int nt = 0; nt < 3; nt++)
        #pragma unroll
        for (int q = 0; q < 4; q++) acc[mt][nt][q] = 0.0f;

        #pragma unroll
        for (int nt = 0; nt < 3; nt++)
        #pragma unroll
        for (int kt = 0; kt < 8; kt++) {
            unsigned b[2];
            b[0] = __float_as_uint(sW2[(kt * 8 + t    ) * 24 + nt * 8 + g]);
            b[1] = __float_as_uint(sW2[(kt * 8 + t + 4) * 24 + nt * 8 + g]);
            mma8(acc[0][nt], a[0][kt], b);
            mma8(acc[1][nt], a[1][kt], b);
        }

        // SH basis -> act cols 0..15 (own row)
        #pragma unroll
        for (int i = 0; i < 16; i++) A[ln * ASTR + i] = tf32r(sh[i]);

        // sigma (col 0) -> global; geometry cols 1..16 -> act cols 16..31
        #pragma unroll
        for (int mt = 0; mt < 2; mt++) {
            const int r = mt * 16 + g;
            #pragma unroll
            for (int nt = 0; nt < 3; nt++) {
                const int n0 = nt * 8 + 2 * t;
                const float v0 = acc[mt][nt][0], v1 = acc[mt][nt][1];
                const float v2 = acc[mt][nt][2], v3 = acc[mt][nt][3];
                if (n0 == 0) {
                    const int p0 = base + r, p1 = base + r + 8;
                    if (p0 < N) out[(size_t)3 * N + p0] = fmaxf(v0, 0.f);
                    if (p1 < N) out[(size_t)3 * N + p1] = fmaxf(v2, 0.f);
                } else if (n0 >= 1 && n0 <= 16) {
                    A[(r    ) * ASTR + 15 + n0] = tf32r(v0);
                    A[(r + 8) * ASTR + 15 + n0] = tf32r(v2);
                }
                const int n1 = n0 + 1;
                if (n1 >= 1 && n1 <= 16) {
                    A[(r    ) * ASTR + 15 + n1] = tf32r(v1);
                    A[(r + 8) * ASTR + 15 + n1] = tf32r(v3);
                }
            }
        }
    }

    // -------- phase B staging: R1 --------
    __syncthreads();
    {
        float* sR1w = sm + OFF_R1;
        for (int i = tid; i < 32 * 64; i += 128) { int r = i >> 6, c = i & 63; sR1w[r * 72 + c] = tf32r(wr1[i]); }
    }
    __syncthreads();

    // =============== rgb layer 1: [32x32] @ [32x64], relu ===============
    {
        const float* sR1 = sm + OFF_R1;
        unsigned a[2][4][4];
        #pragma unroll
        for (int mt = 0; mt < 2; mt++)
        #pragma unroll
        for (int kt = 0; kt < 4; kt++) {
            const int r = mt * 16 + g, k = kt * 8 + t;
            a[mt][kt][0] = __float_as_uint(A[(r    ) * ASTR + k    ]);
            a[mt][kt][1] = __float_as_uint(A[(r + 8) * ASTR + k    ]);
            a[mt][kt][2] = __float_as_uint(A[(r    ) * ASTR + k + 4]);
            a[mt][kt][3] = __float_as_uint(A[(r + 8) * ASTR + k + 4]);
        }
        __syncwarp();
        float acc[2][8][4];
        #pragma unroll
        for (int mt = 0; mt < 2; mt++)
        #pragma unroll
        for (int nt = 0; nt < 8; nt++)
        #pragma unroll
        for (int q = 0; q < 4; q++) acc[mt][nt][q] = 0.0f;

        #pragma unroll
        for (int nt = 0; nt < 8; nt++)
        #pragma unroll
        for (int kt = 0; kt < 4; kt++) {
            unsigned b[2];
            b[0] = __float_as_uint(sR1[(kt * 8 + t    ) * 72 + nt * 8 + g]);
            b[1] = __float_as_uint(sR1[(kt * 8 + t + 4) * 72 + nt * 8 + g]);
            mma8(acc[0][nt], a[0][kt], b);
            mma8(acc[1][nt], a[1][kt], b);
        }
        #pragma unroll
        for (int mt = 0; mt < 2; mt++)
        #pragma unroll
        for (int nt = 0; nt < 8; nt++) {
            const int r = mt * 16 + g, n = nt * 8 + 2 * t;
            A[(r    ) * ASTR + n    ] = tf32r(fmaxf(acc[mt][nt][0], 0.f));
            A[(r    ) * ASTR + n + 1] = tf32r(fmaxf(acc[mt][nt][1], 0.f));
            A[(r + 8) * ASTR + n    ] = tf32r(fmaxf(acc[mt][nt][2], 0.f));
            A[(r + 8) * ASTR + n + 1] = tf32r(fmaxf(acc[mt][nt][3], 0.f));
        }
    }

    // -------- phase C staging: R2, R3 --------
    __syncthreads();
    {
        float* sR2w = sm + OFF_R2;
        float* sR3w = sm + OFF_R3;
        for (int i = tid; i < 64 * 64; i += 128) { int r = i >> 6, c = i & 63; sR2w[r * 72 + c] = tf32r(wr2[i]); }
        for (int i = tid; i < 64 * 8;  i += 128) {
            int r = i >> 3, c = i & 7;
            sR3w[i] = (c < 3) ? tf32r(wr3[r * 3 + c]) : 0.0f;
        }
    }
    __syncthreads();

    // =============== rgb layer 2: [32x64] @ [64x64], relu ===============
    {
        const float* sR2 = sm + OFF_R2;
        unsigned a[2][8][4];
        #pragma unroll
        for (int mt = 0; mt < 2; mt++)
        #pragma unroll
        for (int kt = 0; kt < 8; kt++) {
            const int r = mt * 16 + g, k = kt * 8 + t;
            a[mt][kt][0] = __float_as_uint(A[(r    ) * ASTR + k    ]);
            a[mt][kt][1] = __float_as_uint(A[(r + 8) * ASTR + k    ]);
            a[mt][kt][2] = __float_as_uint(A[(r    ) * ASTR + k + 4]);
            a[mt][kt][3] = __float_as_uint(A[(r + 8) * ASTR + k + 4]);
        }
        __syncwarp();
        float acc[2][8][4];
        #pragma unroll
        for (int mt = 0; mt < 2; mt++)
        #pragma unroll
        for (int nt = 0; nt < 8; nt++)
        #pragma unroll
        for (int q = 0; q < 4; q++) acc[mt][nt][q] = 0.0f;

        #pragma unroll
        for (int nt = 0; nt < 8; nt++)
        #pragma unroll
        for (int kt = 0; kt < 8; kt++) {
            unsigned b[2];
            b[0] = __float_as_uint(sR2[(kt * 8 + t    ) * 72 + nt * 8 + g]);
            b[1] = __float_as_uint(sR2[(kt * 8 + t + 4) * 72 + nt * 8 + g]);
            mma8(acc[0][nt], a[0][kt], b);
            mma8(acc[1][nt], a[1][kt], b);
        }
        #pragma unroll
        for (int mt = 0; mt < 2; mt++)
        #pragma unroll
        for (int nt = 0; nt < 8; nt++) {
            const int r = mt * 16 + g, n = nt * 8 + 2 * t;
            A[(r    ) * ASTR + n    ] = tf32r(fmaxf(acc[mt][nt][0], 0.f));
            A[(r    ) * ASTR + n + 1] = tf32r(fmaxf(acc[mt][nt][1], 0.f));
            A[(r + 8) * ASTR + n    ] = tf32r(fmaxf(acc[mt][nt][2], 0.f));
            A[(r + 8) * ASTR + n + 1] = tf32r(fmaxf(acc[mt][nt][3], 0.f));
        }
    }
    __syncwarp();

    // =============== rgb layer 3: [32x64] @ [64x8] (cols 0..2 real), sigmoid ===============
    {
        const float* sR3 = sm + OFF_R3;
        unsigned a[2][8][4];
        #pragma unroll
        for (int mt = 0; mt < 2; mt++)
        #pragma unroll
        for (int kt = 0; kt < 8; kt++) {
            const int r = mt * 16 + g, k = kt * 8 + t;
            a[mt][kt][0] = __float_as_uint(A[(r    ) * ASTR + k    ]);
            a[mt][kt][1] = __float_as_uint(A[(r + 8) * ASTR + k    ]);
            a[mt][kt][2] = __float_as_uint(A[(r    ) * ASTR + k + 4]);
            a[mt][kt][3] = __float_as_uint(A[(r + 8) * ASTR + k + 4]);
        }
        float acc[2][4];
        #pragma unroll
        for (int mt = 0; mt < 2; mt++)
        #pragma unroll
        for (int q = 0; q < 4; q++) acc[mt][q] = 0.0f;

        #pragma unroll
        for (int kt = 0; kt < 8; kt++) {
            unsigned b[2];
            b[0] = __float_as_uint(sR3[(kt * 8 + t    ) * 8 + g]);
            b[1] = __float_as_uint(sR3[(kt * 8 + t + 4) * 8 + g]);
            mma8(acc[0], a[0][kt], b);
            mma8(acc[1], a[1][kt], b);
        }
        const int n0 = 2 * t;
        #pragma unroll
        for (int mt = 0; mt < 2; mt++) {
            const int r = mt * 16 + g;
            const int p0 = base + r, p1 = base + r + 8;
            if (n0 < 3) {
                if (p0 < N) out[3 * p0 + n0] = 1.0f / (1.0f + __expf(-acc[mt][0]));
                if (p1 < N) out[3 * p1 + n0] = 1.0f / (1.0f + __expf(-acc[mt][2]));
            }
            if (n0 + 1 < 3) {
                if (p0 < N) out[3 * p0 + n0 + 1] = 1.0f / (1.0f + __expf(-acc[mt][1]));
                if (p1 < N) out[3 * p1 + n0 + 1] = 1.0f / (1.0f + __expf(-acc[mt][3]));
            }
        }
    }
}

extern "C" void kernel_launch(void* const* d_in, const int* in_sizes, int n_in,
                              void* d_out, int out_size)
{
    const float* xyz   = (const float*)d_in[0];
    const float* dirp  = (const float*)d_in[1];
    const float* table = (const float*)d_in[2];
    const float* w1    = (const float*)d_in[3];
    const float* w2    = (const float*)d_in[4];
    const float* wr1   = (const float*)d_in[5];
    const float* wr2   = (const float*)d_in[6];
    const float* wr3   = (const float*)d_in[7];
    float* out = (float*)d_out;

    static int smem_set = 0;
    const int smem_bytes = SMEM_FLOATS * sizeof(float);
    if (!smem_set) {
        cudaFuncSetAttribute(nerf_mma_kernel,
                             cudaFuncAttributeMaxDynamicSharedMemorySize, smem_bytes);
        smem_set = 1;
    }

    const int N = in_sizes[0] / 3;

    build_pair_kernel<<<(PAIR_TOTAL + 255) / 256, 256>>>(table);
    encode_kernel<<<(N + 255) / 256, 256>>>(xyz, table, N);
    nerf_mma_kernel<<<(N + 127) / 128, 128, smem_bytes>>>(dirp, w1, w2, wr1, wr2, wr3, out, N);
}